// round 1
// baseline (speedup 1.0000x reference)
#include <cuda_runtime.h>
#include <math.h>

#define Gn 1024
#define Hn 128
#define NNODES 100000
#define NEDGES 500000
#define EPS_LN 1e-5f
#define TILE_E 16

// ---------------- device scratch (static, no allocation) ----------------
__device__ float g_summary[Gn * Hn];
__device__ float g_W2[Hn * 388];     // transposed + padded: [j][k], row stride 388 floats
__device__ float g_u[Hn];
__device__ float g_v[Hn];
__device__ float g_logits[NEDGES];
__device__ float g_tmax[NNODES];
__device__ float g_expsum[NNODES];
__device__ float g_lpg[Gn];
__device__ float g_selsum[Gn];

__device__ __forceinline__ float geluf(float x) {
    return 0.5f * x * (1.0f + erff(x * 0.70710678118654752440f));
}

__device__ __forceinline__ float bsum128(float v, float* red) {
    #pragma unroll
    for (int o = 16; o; o >>= 1) v += __shfl_xor_sync(0xffffffffu, v, o);
    __syncthreads();
    if ((threadIdx.x & 31) == 0) red[threadIdx.x >> 5] = v;
    __syncthreads();
    return red[0] + red[1] + red[2] + red[3];
}

// ---------------- init ----------------
__global__ void k_init() {
    int i = blockIdx.x * blockDim.x + threadIdx.x;
    if (i < NNODES) { g_tmax[i] = -INFINITY; g_expsum[i] = 0.0f; }
    if (i < Gn) { g_lpg[i] = 0.0f; g_selsum[i] = 0.0f; }
}

// ---------------- precompute W' = g .* bw1 (transposed), u, v ----------------
__global__ void k_prep(const float* __restrict__ bw1,
                       const float* __restrict__ blng,
                       const float* __restrict__ blnb) {
    int j = blockIdx.x;          // 0..127 output
    int k = threadIdx.x;         // 0..511
    __shared__ float su[512], sv[512];
    float uu = 0.0f, vv = 0.0f;
    if (k < 384) {
        float w = bw1[k * Hn + j];
        float gk = blng[k];
        g_W2[j * 388 + k] = gk * w;
        uu = gk * w;
        vv = blnb[k] * w;
    } else if (k < 388) {
        g_W2[j * 388 + k] = 0.0f;   // pad
    }
    su[k] = uu; sv[k] = vv;
    __syncthreads();
    for (int s = 256; s > 0; s >>= 1) {
        if (k < s) { su[k] += su[k + s]; sv[k] += sv[k + s]; }
        __syncthreads();
    }
    if (k == 0) { g_u[j] = su[0]; g_v[j] = sv[0]; }
}

// ---------------- start-node attention -> summary ----------------
__global__ void k_start(const float* __restrict__ nodes, const float* __restrict__ qt,
                        const int* __restrict__ locals, const int* __restrict__ ptr) {
    int g = blockIdx.x, t = threadIdx.x;  // 128 threads
    __shared__ float red[4];
    __shared__ float sc[64];
    __shared__ float salpha[64];
    __shared__ int   sidx[64];
    int s0 = ptr[g], s1 = ptr[g + 1];
    int n = s1 - s0; if (n > 64) n = 64; if (n < 0) n = 0;
    float qv = qt[g * Hn + t];
    for (int s = 0; s < n; s++) {
        int nd = locals[s0 + s];
        if (t == 0) sidx[s] = nd;
        float p = nodes[nd * Hn + t] * qv;
        #pragma unroll
        for (int o = 16; o; o >>= 1) p += __shfl_xor_sync(0xffffffffu, p, o);
        if ((t & 31) == 0) red[t >> 5] = p;
        __syncthreads();
        if (t == 0) sc[s] = (red[0] + red[1] + red[2] + red[3]) * 0.08838834764831843f;
        __syncthreads();
    }
    if (t == 0) {
        float m = -INFINITY;
        for (int s = 0; s < n; s++) m = fmaxf(m, sc[s]);
        float d = 0.0f;
        for (int s = 0; s < n; s++) { float e = expf(sc[s] - m); salpha[s] = e; d += e; }
        float inv = 1.0f / d;
        for (int s = 0; s < n; s++) salpha[s] *= inv;
    }
    __syncthreads();
    float acc = 0.0f;
    for (int s = 0; s < n; s++) acc += salpha[s] * nodes[sidx[s] * Hn + t];
    g_summary[g * Hn + t] = acc;
}

// ---------------- context MLP + log_z head (fused per graph) ----------------
__global__ void k_ctx(const float* __restrict__ qt,
                      const float* __restrict__ cw1, const float* __restrict__ cb1,
                      const float* __restrict__ cw2, const float* __restrict__ cb2,
                      const float* __restrict__ ln1g, const float* __restrict__ ln1b,
                      const float* __restrict__ zw1, const float* __restrict__ zb1,
                      const float* __restrict__ zw2, const float* __restrict__ zb2,
                      float* __restrict__ out) {
    int g = blockIdx.x, t = threadIdx.x;  // 128 threads
    __shared__ float xin[256];
    __shared__ float h1[128];
    __shared__ float xh[128];
    __shared__ float red[4];
    xin[t]       = g_summary[g * Hn + t];
    xin[128 + t] = qt[g * Hn + t];
    __syncthreads();
    float a = cb1[t];
    #pragma unroll 4
    for (int k = 0; k < 256; k++) a = fmaf(xin[k], cw1[k * Hn + t], a);
    h1[t] = geluf(a);
    __syncthreads();
    float c = cb2[t];
    #pragma unroll 4
    for (int k = 0; k < 128; k++) c = fmaf(h1[k], cw2[k * Hn + t], c);
    float mean = bsum128(c, red) * (1.0f / 128.0f);
    float d = c - mean;
    float var = bsum128(d * d, red) * (1.0f / 128.0f);
    float nx = d * rsqrtf(var + EPS_LN) * ln1g[t] + ln1b[t];
    xh[t] = nx;
    __syncthreads();
    float a2 = zb1[t];
    #pragma unroll 4
    for (int k = 0; k < 128; k++) a2 = fmaf(xh[k], zw1[k * Hn + t], a2);
    float p = geluf(a2) * zw2[t];
    float lz = bsum128(p, red);
    if (t == 0) out[g * 3 + 0] = lz + zb2[0];
}

// ---------------- edge logits: gather + folded-LN matvec + GELU + dot ----------------
__global__ void __launch_bounds__(256, 1)
k_edge(const float* __restrict__ nodes, const float* __restrict__ qt,
       const float* __restrict__ et,
       const int* __restrict__ ebatch, const int* __restrict__ eidx,
       const float* __restrict__ bb1, const float* __restrict__ bw2,
       const float* __restrict__ bb2) {
    extern __shared__ float4 smem4[];
    float4* ws = smem4;               // [128][97] float4
    float4* xs = ws + 128 * 97;       // [16][96]  float4
    float*  fsm   = (float*)(xs + TILE_E * 96);
    float*  sm_m  = fsm;              // [16]
    float*  sm_is = fsm + 16;         // [16]
    float*  spart = fsm + 32;         // [8][8]

    int t = threadIdx.x;
    int w = t >> 5, lane = t & 31;

    // stage weights into smem once per block
    const float4* W2v = (const float4*)g_W2;
    for (int i = t; i < 128 * 97; i += 256) ws[i] = W2v[i];

    int j = t & 127;
    int half = t >> 7;
    int eb = half * 8;
    float uj = g_u[j], vj = g_v[j], bj = bb1[j], w2j = bw2[j];
    float bias2 = bb2[0];

    const int ntiles = (NEDGES + TILE_E - 1) / TILE_E;
    for (int tile = blockIdx.x; tile < ntiles; tile += gridDim.x) {
        int e0 = tile * TILE_E;
        __syncthreads();  // xs/spart reuse barrier
        // gather: 48 segments of 128 floats (edge_tokens | question | tail node)
        for (int s = w; s < TILE_E * 3; s += 8) {
            int el = s & 15, part = s >> 4;
            int e = e0 + el;
            float4 v;
            if (e < NEDGES) {
                const float4* src;
                if (part == 0)      src = (const float4*)(et + (size_t)e * Hn);
                else if (part == 1) src = (const float4*)(qt + (size_t)ebatch[e] * Hn);
                else                src = (const float4*)(nodes + (size_t)eidx[NEDGES + e] * Hn);
                v = src[lane];
            } else { v = make_float4(0.f, 0.f, 0.f, 0.f); }
            xs[el * 96 + part * 32 + lane] = v;
        }
        __syncthreads();
        // per-edge LN stats
        for (int e = w; e < TILE_E; e += 8) {
            float s1 = 0.f, s2 = 0.f;
            const float4* xr = xs + e * 96;
            #pragma unroll
            for (int i = lane; i < 96; i += 32) {
                float4 v = xr[i];
                s1 += v.x + v.y + v.z + v.w;
                s2 += v.x * v.x + v.y * v.y + v.z * v.z + v.w * v.w;
            }
            #pragma unroll
            for (int o = 16; o; o >>= 1) {
                s1 += __shfl_xor_sync(0xffffffffu, s1, o);
                s2 += __shfl_xor_sync(0xffffffffu, s2, o);
            }
            if (lane == 0) {
                float m = s1 * (1.0f / 384.0f);
                float var = s2 * (1.0f / 384.0f) - m * m;
                sm_m[e] = m;
                sm_is[e] = rsqrtf(fmaxf(var, 0.0f) + EPS_LN);
            }
        }
        __syncthreads();
        // matvec: this thread = output j, edges eb..eb+7
        float acc[8];
        #pragma unroll
        for (int e = 0; e < 8; e++) acc[e] = 0.0f;
        const float4* wr = ws + j * 97;
        const float4* xr = xs + eb * 96;
        #pragma unroll 4
        for (int kk = 0; kk < 96; kk++) {
            float4 wv = wr[kk];
            #pragma unroll
            for (int e = 0; e < 8; e++) {
                float4 xv = xr[e * 96 + kk];
                acc[e] = fmaf(xv.x, wv.x, fmaf(xv.y, wv.y, fmaf(xv.z, wv.z, fmaf(xv.w, wv.w, acc[e]))));
            }
        }
        // epilogue: folded LN + GELU + dot(bw2)
        #pragma unroll
        for (int e = 0; e < 8; e++) {
            float y = (acc[e] - sm_m[eb + e] * uj) * sm_is[eb + e] + vj + bj;
            float p = geluf(y) * w2j;
            #pragma unroll
            for (int o = 16; o; o >>= 1) p += __shfl_xor_sync(0xffffffffu, p, o);
            if (lane == 0) spart[w * 8 + e] = p;
        }
        __syncthreads();
        if (t < TILE_E) {
            int hh = t >> 3, el = t & 7;
            float sum = 0.0f;
            #pragma unroll
            for (int ww = 0; ww < 4; ww++) sum += spart[(hh * 4 + ww) * 8 + el];
            int e = e0 + t;
            if (e < NEDGES) g_logits[e] = sum + bias2;
        }
    }
}

// ---------------- segment max over target nodes ----------------
__global__ void k_smax(const int* __restrict__ eidx) {
    int e = blockIdx.x * blockDim.x + threadIdx.x;
    if (e >= NEDGES) return;
    int tg = eidx[NEDGES + e];
    float v = g_logits[e];
    if (v >= 0.0f) atomicMax((int*)&g_tmax[tg], __float_as_int(v));
    else           atomicMin((unsigned int*)&g_tmax[tg], __float_as_uint(v));
}

// ---------------- segment exp-sum ----------------
__global__ void k_sexp(const int* __restrict__ eidx) {
    int e = blockIdx.x * blockDim.x + threadIdx.x;
    if (e >= NEDGES) return;
    int tg = eidx[NEDGES + e];
    atomicAdd(&g_expsum[tg], expf(g_logits[e] - g_tmax[tg]));
}

// ---------------- per-graph selected log-prob sums (run-aggregated atomics) ----------------
__global__ void k_lpb(const int* __restrict__ eidx, const int* __restrict__ ebatch,
                      const int* __restrict__ mask) {
    const int CH = 16;
    int base = (blockIdx.x * blockDim.x + threadIdx.x) * CH;
    if (base >= NEDGES) return;
    int end = base + CH; if (end > NEDGES) end = NEDGES;
    int cur = -1; float aL = 0.0f, aS = 0.0f;
    for (int e = base; e < end; e++) {
        int b = ebatch[e];
        if (b != cur) {
            if (cur >= 0 && (aL != 0.0f || aS != 0.0f)) {
                atomicAdd(&g_lpg[cur], aL);
                atomicAdd(&g_selsum[cur], aS);
            }
            cur = b; aL = 0.0f; aS = 0.0f;
        }
        if (mask[e] != 0) {   // works for int32 {0,1} and float32 {0.0,1.0} encodings
            int tg = eidx[NEDGES + e];
            float lp = (g_logits[e] - g_tmax[tg]) - logf(g_expsum[tg]);
            aL += lp; aS += 1.0f;
        }
    }
    if (cur >= 0 && (aL != 0.0f || aS != 0.0f)) {
        atomicAdd(&g_lpg[cur], aL);
        atomicAdd(&g_selsum[cur], aS);
    }
}

// ---------------- finalize ----------------
__global__ void k_fin(float* __restrict__ out) {
    int g = threadIdx.x;  // 1024 threads, 1 block
    __shared__ float rs[32], rc[32];
    __shared__ float s_res;
    float lpg = g_lpg[g];
    float has = (g_selsum[g] > 0.0f) ? 1.0f : 0.0f;
    float v1 = -lpg * has, v2 = has;
    #pragma unroll
    for (int o = 16; o; o >>= 1) {
        v1 += __shfl_xor_sync(0xffffffffu, v1, o);
        v2 += __shfl_xor_sync(0xffffffffu, v2, o);
    }
    if ((g & 31) == 0) { rs[g >> 5] = v1; rc[g >> 5] = v2; }
    __syncthreads();
    if (g < 32) {
        float a = rs[g], b = rc[g];
        #pragma unroll
        for (int o = 16; o; o >>= 1) {
            a += __shfl_xor_sync(0xffffffffu, a, o);
            b += __shfl_xor_sync(0xffffffffu, b, o);
        }
        if (g == 0) s_res = a / fmaxf(b, 1.0f);
    }
    __syncthreads();
    out[g * 3 + 1] = lpg;
    out[g * 3 + 2] = s_res;
}

// ---------------- host ----------------
extern "C" void kernel_launch(void* const* d_in, const int* in_sizes, int n_in,
                              void* d_out, int out_size) {
    // Two plausible metadata orderings: setup_inputs dict order vs reference()
    // signature order. Disambiguate via in_sizes[3] (4096 = start_node_locals).
    int I_node, I_q, I_edge, I_loc, I_ptr, I_eb, I_mask, I_eidx;
    int I_ln1g, I_ln1b, I_zw1, I_zb1, I_zw2, I_zb2;
    int I_cw1, I_cb1, I_cw2, I_cb2, I_blng, I_blnb, I_bw1, I_bb1, I_bw2, I_bb2;
    if (in_sizes[3] == 4096) {  // dict order
        I_node = 0; I_q = 1; I_edge = 2; I_loc = 3; I_ptr = 4; I_eb = 5; I_mask = 6; I_eidx = 7;
        I_ln1g = 8; I_ln1b = 9; I_zw1 = 10; I_zb1 = 11; I_zw2 = 12; I_zb2 = 13;
        I_cw1 = 14; I_cb1 = 15; I_cw2 = 16; I_cb2 = 17;
        I_blng = 18; I_blnb = 19; I_bw1 = 20; I_bb1 = 21; I_bw2 = 22; I_bb2 = 23;
    } else {                    // signature order
        I_node = 0; I_q = 1; I_edge = 2;
        I_ln1g = 3; I_ln1b = 4; I_zw1 = 5; I_zb1 = 6; I_zw2 = 7; I_zb2 = 8;
        I_cw1 = 9; I_cb1 = 10; I_cw2 = 11; I_cb2 = 12;
        I_blng = 13; I_blnb = 14; I_bw1 = 15; I_bb1 = 16; I_bw2 = 17; I_bb2 = 18;
        I_loc = 19; I_ptr = 20; I_eb = 21; I_mask = 22; I_eidx = 23;
    }

    const float* nodes = (const float*)d_in[I_node];
    const float* qt    = (const float*)d_in[I_q];
    const float* et    = (const float*)d_in[I_edge];
    const int*   locs  = (const int*)d_in[I_loc];
    const int*   ptr   = (const int*)d_in[I_ptr];
    const int*   ebat  = (const int*)d_in[I_eb];
    const int*   mask  = (const int*)d_in[I_mask];
    const int*   eidx  = (const int*)d_in[I_eidx];
    float* out = (float*)d_out;

    int dev = 0, nsm = 148;
    cudaGetDevice(&dev);
    cudaDeviceGetAttribute(&nsm, cudaDevAttrMultiProcessorCount, dev);

    const size_t edge_smem = (size_t)(128 * 97 + TILE_E * 96) * sizeof(float4) + 96 * sizeof(float);
    cudaFuncSetAttribute(k_edge, cudaFuncAttributeMaxDynamicSharedMemorySize, (int)edge_smem);

    k_init<<<(NNODES + 255) / 256, 256>>>();
    k_prep<<<128, 512>>>((const float*)d_in[I_bw1], (const float*)d_in[I_blng],
                         (const float*)d_in[I_blnb]);
    k_start<<<Gn, 128>>>(nodes, qt, locs, ptr);
    k_ctx<<<Gn, 128>>>(qt,
                       (const float*)d_in[I_cw1], (const float*)d_in[I_cb1],
                       (const float*)d_in[I_cw2], (const float*)d_in[I_cb2],
                       (const float*)d_in[I_ln1g], (const float*)d_in[I_ln1b],
                       (const float*)d_in[I_zw1], (const float*)d_in[I_zb1],
                       (const float*)d_in[I_zw2], (const float*)d_in[I_zb2],
                       out);
    k_edge<<<nsm, 256, edge_smem>>>(nodes, qt, et, ebat, eidx,
                                    (const float*)d_in[I_bb1], (const float*)d_in[I_bw2],
                                    (const float*)d_in[I_bb2]);
    k_smax<<<(NEDGES + 255) / 256, 256>>>(eidx);
    k_sexp<<<(NEDGES + 255) / 256, 256>>>(eidx);
    k_lpb<<<((NEDGES + 15) / 16 + 255) / 256, 256>>>(eidx, ebat, mask);
    k_fin<<<1, 1024>>>(out);
}

// round 3
// speedup vs baseline: 4.1709x; 4.1709x over previous
#include <cuda_runtime.h>
#include <cuda_bf16.h>
#include <math.h>
#include <stdint.h>

#define Gn 1024
#define Hn 128
#define NNODES 100000
#define NEDGES 500000
#define EPS_LN 1e-5f
#define NTILES ((NEDGES + 127) / 128)

// ---------------- device scratch ----------------
__device__ float g_summary[Gn * Hn];
__device__ float g_u[Hn];
__device__ float g_vb[Hn];
__device__ uint4 g_Wswhi[6144];   // 98304 B: [chunk][j][64k] bf16, XOR-16B swizzled rows
__device__ uint4 g_Wswlo[6144];
__device__ float g_logits[NEDGES];
__device__ float g_tmax[NNODES];
__device__ float g_expsum[NNODES];
__device__ float g_lpg[Gn];
__device__ float g_selsum[Gn];

// smem byte offsets (total = 232448, the sm_10x opt-in max)
#define SM_PU    0
#define SM_PVB   512
#define SM_PW2   1024
#define SM_S1    1536
#define SM_S2    2048
#define SM_WH    3072
#define SM_WL    101376
#define SM_AHI   199680
#define SM_ALO   216064
#define SM_TOTAL 232448

__device__ __forceinline__ uint32_t smem_u32(const void* p) {
    uint32_t a;
    asm("{ .reg .u64 t; cvta.to.shared.u64 t, %1; cvt.u32.u64 %0, t; }" : "=r"(a) : "l"(p));
    return a;
}
#define LDMX4(r, a) \
    asm volatile("ldmatrix.sync.aligned.m8n8.x4.shared.b16 {%0,%1,%2,%3}, [%4];" \
        : "=r"((r)[0]), "=r"((r)[1]), "=r"((r)[2]), "=r"((r)[3]) : "r"(a))

__device__ __forceinline__ void mma_bf16(float* d, const uint32_t* a, const uint32_t* b) {
    asm volatile("mma.sync.aligned.m16n8k16.row.col.f32.bf16.bf16.f32 "
        "{%0,%1,%2,%3}, {%4,%5,%6,%7}, {%8,%9}, {%0,%1,%2,%3};"
        : "+f"(d[0]), "+f"(d[1]), "+f"(d[2]), "+f"(d[3])
        : "r"(a[0]), "r"(a[1]), "r"(a[2]), "r"(a[3]), "r"(b[0]), "r"(b[1]));
}
__device__ __forceinline__ uint32_t packbf(__nv_bfloat16 a, __nv_bfloat16 b) {
    return (uint32_t)__bfloat16_as_ushort(a) | ((uint32_t)__bfloat16_as_ushort(b) << 16);
}
__device__ __forceinline__ float geluf(float x) {
    return 0.5f * x * (1.0f + erff(x * 0.70710678118654752440f));
}

// ---------------- init ----------------
__global__ void k_init() {
    int i = blockIdx.x * blockDim.x + threadIdx.x;
    if (i < NNODES) { g_tmax[i] = -INFINITY; g_expsum[i] = 0.0f; }
    if (i < Gn) { g_lpg[i] = 0.0f; g_selsum[i] = 0.0f; }
}

// ---------------- prep: W' = g.*W -> bf16 hi/lo swizzled; u, vb ----------------
__global__ void k_prep(const float* __restrict__ bw1, const float* __restrict__ blng,
                       const float* __restrict__ blnb, const float* __restrict__ bb1) {
    int j = blockIdx.x;     // output 0..127
    int k = threadIdx.x;    // 0..383
    __shared__ float rs[12], rv[12];
    float wraw = bw1[k * Hn + j];
    float wv = blng[k] * wraw;
    float vv = blnb[k] * wraw;
    __nv_bfloat16 h = __float2bfloat16(wv);
    __nv_bfloat16 l = __float2bfloat16(wv - __bfloat162float(h));
    int chunk = k >> 6, kloc = k & 63;
    uint32_t off = (uint32_t)(chunk * 16384 + j * 128 + ((kloc * 2) ^ ((j & 7) << 4)));
    *(unsigned short*)((char*)g_Wswhi + off) = __bfloat16_as_ushort(h);
    *(unsigned short*)((char*)g_Wswlo + off) = __bfloat16_as_ushort(l);
    float uu = wv;
    #pragma unroll
    for (int o = 16; o; o >>= 1) {
        uu += __shfl_xor_sync(0xffffffffu, uu, o);
        vv += __shfl_xor_sync(0xffffffffu, vv, o);
    }
    if ((k & 31) == 0) { rs[k >> 5] = uu; rv[k >> 5] = vv; }
    __syncthreads();
    if (k == 0) {
        float U = 0.f, V = 0.f;
        for (int i = 0; i < 12; i++) { U += rs[i]; V += rv[i]; }
        g_u[j] = U;
        g_vb[j] = V + bb1[j];
    }
}

// ---------------- start-node attention -> summary ----------------
__global__ void k_start(const float* __restrict__ nodes, const float* __restrict__ qt,
                        const int* __restrict__ locals, const int* __restrict__ ptr) {
    int g = blockIdx.x, t = threadIdx.x;
    __shared__ float red[4];
    __shared__ float sc[64];
    __shared__ float salpha[64];
    __shared__ int   sidx[64];
    int s0 = ptr[g], s1 = ptr[g + 1];
    int n = s1 - s0; if (n > 64) n = 64; if (n < 0) n = 0;
    float qv = qt[g * Hn + t];
    for (int s = 0; s < n; s++) {
        int nd = locals[s0 + s];
        if (t == 0) sidx[s] = nd;
        float p = nodes[nd * Hn + t] * qv;
        #pragma unroll
        for (int o = 16; o; o >>= 1) p += __shfl_xor_sync(0xffffffffu, p, o);
        if ((t & 31) == 0) red[t >> 5] = p;
        __syncthreads();
        if (t == 0) sc[s] = (red[0] + red[1] + red[2] + red[3]) * 0.08838834764831843f;
        __syncthreads();
    }
    if (t == 0) {
        float m = -INFINITY;
        for (int s = 0; s < n; s++) m = fmaxf(m, sc[s]);
        float d = 0.0f;
        for (int s = 0; s < n; s++) { float e = expf(sc[s] - m); salpha[s] = e; d += e; }
        float inv = 1.0f / d;
        for (int s = 0; s < n; s++) salpha[s] *= inv;
    }
    __syncthreads();
    float acc = 0.0f;
    for (int s = 0; s < n; s++) acc += salpha[s] * nodes[sidx[s] * Hn + t];
    g_summary[g * Hn + t] = acc;
}

// ---------------- context MLP + log_z head ----------------
__device__ __forceinline__ float bsum128(float v, float* red) {
    #pragma unroll
    for (int o = 16; o; o >>= 1) v += __shfl_xor_sync(0xffffffffu, v, o);
    __syncthreads();
    if ((threadIdx.x & 31) == 0) red[threadIdx.x >> 5] = v;
    __syncthreads();
    return red[0] + red[1] + red[2] + red[3];
}
__global__ void k_ctx(const float* __restrict__ qt,
                      const float* __restrict__ cw1, const float* __restrict__ cb1,
                      const float* __restrict__ cw2, const float* __restrict__ cb2,
                      const float* __restrict__ ln1g, const float* __restrict__ ln1b,
                      const float* __restrict__ zw1, const float* __restrict__ zb1,
                      const float* __restrict__ zw2, const float* __restrict__ zb2,
                      float* __restrict__ out) {
    int g = blockIdx.x, t = threadIdx.x;
    __shared__ float xin[256];
    __shared__ float h1[128];
    __shared__ float xh[128];
    __shared__ float red[4];
    xin[t]       = g_summary[g * Hn + t];
    xin[128 + t] = qt[g * Hn + t];
    __syncthreads();
    float a = cb1[t];
    #pragma unroll 4
    for (int k = 0; k < 256; k++) a = fmaf(xin[k], cw1[k * Hn + t], a);
    h1[t] = geluf(a);
    __syncthreads();
    float c = cb2[t];
    #pragma unroll 4
    for (int k = 0; k < 128; k++) c = fmaf(h1[k], cw2[k * Hn + t], c);
    float mean = bsum128(c, red) * (1.0f / 128.0f);
    float d = c - mean;
    float var = bsum128(d * d, red) * (1.0f / 128.0f);
    float nx = d * rsqrtf(var + EPS_LN) * ln1g[t] + ln1b[t];
    xh[t] = nx;
    __syncthreads();
    float a2 = zb1[t];
    #pragma unroll 4
    for (int k = 0; k < 128; k++) a2 = fmaf(xh[k], zw1[k * Hn + t], a2);
    float p = geluf(a2) * zw2[t];
    float lz = bsum128(p, red);
    if (t == 0) out[g * 3 + 0] = lz + zb2[0];
}

// ---------------- edge logits: 3-term bf16-split GEMM via mma.sync ----------------
__global__ void __launch_bounds__(256, 1)
k_edge(const float* __restrict__ nodes, const float* __restrict__ qt,
       const float* __restrict__ et,
       const int* __restrict__ ebatch, const int* __restrict__ eidx,
       const float* __restrict__ bw2, const float* __restrict__ bb2) {
    extern __shared__ char smem[];
    uint32_t sb = smem_u32(smem);
    int t = threadIdx.x, w = t >> 5, lane = t & 31;
    int warp_m = w >> 2, warp_n = w & 3;
    int eg = t >> 4;           // 0..15: edge group
    int kg = t & 15;           // k-segment within row
    int cb = kg * 8;           // byte col of this thread's 4 bf16

    // stage weights + params
    {
        uint4* dh = (uint4*)(smem + SM_WH);
        uint4* dl = (uint4*)(smem + SM_WL);
        for (int i = t; i < 6144; i += 256) { dh[i] = g_Wswhi[i]; dl[i] = g_Wswlo[i]; }
    }
    float* pu  = (float*)(smem + SM_PU);
    float* pvb = (float*)(smem + SM_PVB);
    float* pw2 = (float*)(smem + SM_PW2);
    float* s1  = (float*)(smem + SM_S1);
    float* s2  = (float*)(smem + SM_S2);
    if (t < 128) { pu[t] = g_u[t]; pvb[t] = g_vb[t]; pw2[t] = bw2[t]; }
    __syncthreads();
    float bias2 = bb2[0];

    for (int tile = blockIdx.x; tile < NTILES; tile += gridDim.x) {
        int e0 = tile * 128;
        float acc[4][4][4];
        #pragma unroll
        for (int a = 0; a < 4; a++)
            #pragma unroll
            for (int b = 0; b < 4; b++)
                #pragma unroll
                for (int d = 0; d < 4; d++) acc[a][b][d] = 0.0f;
        float lnS[8], lnQ[8];
        #pragma unroll
        for (int i = 0; i < 8; i++) { lnS[i] = 0.0f; lnQ[i] = 0.0f; }
        float4 gv[8];

        #define LOADCHUNK(c) do { \
            int part = (c) >> 1; \
            int fo = ((c) & 1) * 64 + kg * 4; \
            _Pragma("unroll") \
            for (int i = 0; i < 8; i++) { \
                int e = e0 + eg + i * 16; \
                float4 v = make_float4(0.f, 0.f, 0.f, 0.f); \
                if (e < NEDGES) { \
                    const float* src; \
                    if (part == 0)      src = et + (size_t)e * Hn + fo; \
                    else if (part == 1) src = qt + (size_t)ebatch[e] * Hn + fo; \
                    else                src = nodes + (size_t)eidx[NEDGES + e] * Hn + fo; \
                    v = *(const float4*)src; \
                } \
                gv[i] = v; \
            } } while (0)

        #define CONV() do { \
            _Pragma("unroll") \
            for (int i = 0; i < 8; i++) { \
                float4 v = gv[i]; int el = eg + i * 16; \
                lnS[i] += v.x + v.y + v.z + v.w; \
                lnQ[i] += fmaf(v.x, v.x, fmaf(v.y, v.y, fmaf(v.z, v.z, v.w * v.w))); \
                __nv_bfloat16 hx = __float2bfloat16(v.x), hy = __float2bfloat16(v.y); \
                __nv_bfloat16 hz = __float2bfloat16(v.z), hw = __float2bfloat16(v.w); \
                __nv_bfloat16 lx = __float2bfloat16(v.x - __bfloat162float(hx)); \
                __nv_bfloat16 ly = __float2bfloat16(v.y - __bfloat162float(hy)); \
                __nv_bfloat16 lz = __float2bfloat16(v.z - __bfloat162float(hz)); \
                __nv_bfloat16 lw = __float2bfloat16(v.w - __bfloat162float(hw)); \
                uint2 H; H.x = packbf(hx, hy); H.y = packbf(hz, hw); \
                uint2 L; L.x = packbf(lx, ly); L.y = packbf(lz, lw); \
                uint32_t off = (uint32_t)(el * 128 + (cb ^ ((el & 7) << 4))); \
                *(uint2*)(smem + SM_AHI + off) = H; \
                *(uint2*)(smem + SM_ALO + off) = L; \
            } } while (0)

        LOADCHUNK(0);
        #pragma unroll 1
        for (int c = 0; c < 6; c++) {
            CONV();
            __syncthreads();
            if (c < 5) {
                switch (c) {
                    case 0: LOADCHUNK(1); break;
                    case 1: LOADCHUNK(2); break;
                    case 2: LOADCHUNK(3); break;
                    case 3: LOADCHUNK(4); break;
                    case 4: LOADCHUNK(5); break;
                }
            }
            // MMA over this 64-wide K chunk
            uint32_t whc = sb + SM_WH + c * 16384;
            uint32_t wlc = sb + SM_WL + c * 16384;
            #pragma unroll
            for (int ks = 0; ks < 4; ks++) {
                int k0b = ks * 32;
                uint32_t ah[4][4], al[4][4], bh[8], bl[8];
                #pragma unroll
                for (int mt = 0; mt < 4; mt++) {
                    int row = warp_m * 64 + mt * 16 + (lane & 7) + ((lane >> 3) & 1) * 8;
                    int colb = k0b + (lane >> 4) * 16;
                    uint32_t off = (uint32_t)(row * 128 + (colb ^ ((row & 7) << 4)));
                    LDMX4(ah[mt], sb + SM_AHI + off);
                    LDMX4(al[mt], sb + SM_ALO + off);
                }
                #pragma unroll
                for (int bt = 0; bt < 2; bt++) {
                    int j = warp_n * 32 + bt * 16 + (lane & 7) + (lane >> 4) * 8;
                    int kb = k0b + ((lane >> 3) & 1) * 16;
                    uint32_t off = (uint32_t)(j * 128 + (kb ^ ((j & 7) << 4)));
                    LDMX4(&bh[bt * 4], whc + off);
                    LDMX4(&bl[bt * 4], wlc + off);
                }
                #pragma unroll
                for (int mt = 0; mt < 4; mt++)
                    #pragma unroll
                    for (int nt = 0; nt < 4; nt++) {
                        const uint32_t* bph = &bh[(nt >> 1) * 4 + (nt & 1) * 2];
                        const uint32_t* bpl = &bl[(nt >> 1) * 4 + (nt & 1) * 2];
                        mma_bf16(acc[mt][nt], ah[mt], bph);
                        mma_bf16(acc[mt][nt], al[mt], bph);
                        mma_bf16(acc[mt][nt], ah[mt], bpl);
                    }
            }
            __syncthreads();
        }
        #undef LOADCHUNK
        #undef CONV

        // LN stat totals -> smem
        #pragma unroll
        for (int i = 0; i < 8; i++) {
            float a = lnS[i], b = lnQ[i];
            #pragma unroll
            for (int o = 8; o; o >>= 1) {
                a += __shfl_xor_sync(0xffffffffu, a, o);
                b += __shfl_xor_sync(0xffffffffu, b, o);
            }
            if (kg == 0) { s1[eg + i * 16] = a; s2[eg + i * 16] = b; }
        }
        __syncthreads();

        // epilogue: folded LN + GELU + dot(w2)
        int g = lane >> 2, cpair = (lane & 3) * 2;
        float* spart = (float*)(smem + SM_AHI);  // 4x128, A buffer is dead now
        #pragma unroll
        for (int mt = 0; mt < 4; mt++) {
            #pragma unroll
            for (int half = 0; half < 2; half++) {
                int row = warp_m * 64 + mt * 16 + half * 8 + g;
                float m  = s1[row] * (1.0f / 384.0f);
                float var = s2[row] * (1.0f / 384.0f) - m * m;
                float is = rsqrtf(fmaxf(var, 0.0f) + EPS_LN);
                float pv = 0.0f;
                #pragma unroll
                for (int nt = 0; nt < 4; nt++) {
                    int j0 = warp_n * 32 + nt * 8 + cpair;
                    float d0 = acc[mt][nt][half * 2 + 0];
                    float d1 = acc[mt][nt][half * 2 + 1];
                    float y0 = (d0 - m * pu[j0])     * is + pvb[j0];
                    float y1 = (d1 - m * pu[j0 + 1]) * is + pvb[j0 + 1];
                    pv = fmaf(geluf(y0), pw2[j0], pv);
                    pv = fmaf(geluf(y1), pw2[j0 + 1], pv);
                }
                pv += __shfl_xor_sync(0xffffffffu, pv, 1);
                pv += __shfl_xor_sync(0xffffffffu, pv, 2);
                if ((lane & 3) == 0) spart[warp_n * 128 + row] = pv;
            }
        }
        __syncthreads();
        if (t < 128) {
            int e = e0 + t;
            if (e < NEDGES)
                g_logits[e] = spart[t] + spart[128 + t] + spart[256 + t] + spart[384 + t] + bias2;
        }
        __syncthreads();
    }
}

// ---------------- segment softmax + per-graph sums ----------------
__global__ void k_smax(const int* __restrict__ eidx) {
    int e = blockIdx.x * blockDim.x + threadIdx.x;
    if (e >= NEDGES) return;
    int tg = eidx[NEDGES + e];
    float v = g_logits[e];
    if (v >= 0.0f) atomicMax((int*)&g_tmax[tg], __float_as_int(v));
    else           atomicMin((unsigned int*)&g_tmax[tg], __float_as_uint(v));
}
__global__ void k_sexp(const int* __restrict__ eidx) {
    int e = blockIdx.x * blockDim.x + threadIdx.x;
    if (e >= NEDGES) return;
    int tg = eidx[NEDGES + e];
    atomicAdd(&g_expsum[tg], expf(g_logits[e] - g_tmax[tg]));
}
__global__ void k_lpb(const int* __restrict__ eidx, const int* __restrict__ ebatch,
                      const int* __restrict__ mask) {
    const int CH = 16;
    int base = (blockIdx.x * blockDim.x + threadIdx.x) * CH;
    if (base >= NEDGES) return;
    int end = base + CH; if (end > NEDGES) end = NEDGES;
    int cur = -1; float aL = 0.0f, aS = 0.0f;
    for (int e = base; e < end; e++) {
        int b = ebatch[e];
        if (b != cur) {
            if (cur >= 0 && (aL != 0.0f || aS != 0.0f)) {
                atomicAdd(&g_lpg[cur], aL);
                atomicAdd(&g_selsum[cur], aS);
            }
            cur = b; aL = 0.0f; aS = 0.0f;
        }
        if (mask[e] != 0) {
            int tg = eidx[NEDGES + e];
            float lp = (g_logits[e] - g_tmax[tg]) - logf(g_expsum[tg]);
            aL += lp; aS += 1.0f;
        }
    }
    if (cur >= 0 && (aL != 0.0f || aS != 0.0f)) {
        atomicAdd(&g_lpg[cur], aL);
        atomicAdd(&g_selsum[cur], aS);
    }
}
__global__ void k_fin(float* __restrict__ out) {
    int g = threadIdx.x;
    __shared__ float rs[32], rc[32];
    __shared__ float s_res;
    float lpg = g_lpg[g];
    float has = (g_selsum[g] > 0.0f) ? 1.0f : 0.0f;
    float v1 = -lpg * has, v2 = has;
    #pragma unroll
    for (int o = 16; o; o >>= 1) {
        v1 += __shfl_xor_sync(0xffffffffu, v1, o);
        v2 += __shfl_xor_sync(0xffffffffu, v2, o);
    }
    if ((g & 31) == 0) { rs[g >> 5] = v1; rc[g >> 5] = v2; }
    __syncthreads();
    if (g < 32) {
        float a = rs[g], b = rc[g];
        #pragma unroll
        for (int o = 16; o; o >>= 1) {
            a += __shfl_xor_sync(0xffffffffu, a, o);
            b += __shfl_xor_sync(0xffffffffu, b, o);
        }
        if (g == 0) s_res = a / fmaxf(b, 1.0f);
    }
    __syncthreads();
    out[g * 3 + 1] = lpg;
    out[g * 3 + 2] = s_res;
}

// ---------------- host ----------------
extern "C" void kernel_launch(void* const* d_in, const int* in_sizes, int n_in,
                              void* d_out, int out_size) {
    int I_node, I_q, I_edge, I_loc, I_ptr, I_eb, I_mask, I_eidx;
    int I_ln1g, I_ln1b, I_zw1, I_zb1, I_zw2, I_zb2;
    int I_cw1, I_cb1, I_cw2, I_cb2, I_blng, I_blnb, I_bw1, I_bb1, I_bw2, I_bb2;
    if (in_sizes[3] == 4096) {  // dict order
        I_node = 0; I_q = 1; I_edge = 2; I_loc = 3; I_ptr = 4; I_eb = 5; I_mask = 6; I_eidx = 7;
        I_ln1g = 8; I_ln1b = 9; I_zw1 = 10; I_zb1 = 11; I_zw2 = 12; I_zb2 = 13;
        I_cw1 = 14; I_cb1 = 15; I_cw2 = 16; I_cb2 = 17;
        I_blng = 18; I_blnb = 19; I_bw1 = 20; I_bb1 = 21; I_bw2 = 22; I_bb2 = 23;
    } else {                    // signature order
        I_node = 0; I_q = 1; I_edge = 2;
        I_ln1g = 3; I_ln1b = 4; I_zw1 = 5; I_zb1 = 6; I_zw2 = 7; I_zb2 = 8;
        I_cw1 = 9; I_cb1 = 10; I_cw2 = 11; I_cb2 = 12;
        I_blng = 13; I_blnb = 14; I_bw1 = 15; I_bb1 = 16; I_bw2 = 17; I_bb2 = 18;
        I_loc = 19; I_ptr = 20; I_eb = 21; I_mask = 22; I_eidx = 23;
    }

    const float* nodes = (const float*)d_in[I_node];
    const float* qt    = (const float*)d_in[I_q];
    const float* et    = (const float*)d_in[I_edge];
    const int*   locs  = (const int*)d_in[I_loc];
    const int*   ptr   = (const int*)d_in[I_ptr];
    const int*   ebat  = (const int*)d_in[I_eb];
    const int*   mask  = (const int*)d_in[I_mask];
    const int*   eidx  = (const int*)d_in[I_eidx];
    float* out = (float*)d_out;

    int dev = 0, nsm = 148;
    cudaGetDevice(&dev);
    cudaDeviceGetAttribute(&nsm, cudaDevAttrMultiProcessorCount, dev);

    static int smem_set = 0;
    if (!smem_set) {
        cudaFuncSetAttribute(k_edge, cudaFuncAttributeMaxDynamicSharedMemorySize, SM_TOTAL);
        smem_set = 1;
    }

    k_init<<<(NNODES + 255) / 256, 256>>>();
    k_prep<<<128, 384>>>((const float*)d_in[I_bw1], (const float*)d_in[I_blng],
                         (const float*)d_in[I_blnb], (const float*)d_in[I_bb1]);
    k_start<<<Gn, 128>>>(nodes, qt, locs, ptr);
    k_ctx<<<Gn, 128>>>(qt,
                       (const float*)d_in[I_cw1], (const float*)d_in[I_cb1],
                       (const float*)d_in[I_cw2], (const float*)d_in[I_cb2],
                       (const float*)d_in[I_ln1g], (const float*)d_in[I_ln1b],
                       (const float*)d_in[I_zw1], (const float*)d_in[I_zb1],
                       (const float*)d_in[I_zw2], (const float*)d_in[I_zb2],
                       out);
    k_edge<<<nsm, 256, SM_TOTAL>>>(nodes, qt, et, ebat, eidx,
                                   (const float*)d_in[I_bw2], (const float*)d_in[I_bb2]);
    k_smax<<<(NEDGES + 255) / 256, 256>>>(eidx);
    k_sexp<<<(NEDGES + 255) / 256, 256>>>(eidx);
    k_lpb<<<((NEDGES + 15) / 16 + 255) / 256, 256>>>(eidx, ebat, mask);
    k_fin<<<1, 1024>>>(out);
}

// round 5
// speedup vs baseline: 4.9417x; 1.1848x over previous
#include <cuda_runtime.h>
#include <cuda_bf16.h>
#include <math.h>
#include <stdint.h>

#define Gn 1024
#define Hn 128
#define NNODES 100000
#define NEDGES 500000
#define EPS_LN 1e-5f
#define NTILES ((NEDGES + 127) / 128)

// ---------------- device scratch ----------------
__device__ float g_u[Hn];
__device__ float g_vb[Hn];
__device__ uint4 g_Wsw[6144];    // 98304 B: [chunk][j][64k] bf16, XOR-16B swizzled rows
__device__ float g_logits[NEDGES];
__device__ float g_tmax[NNODES];
__device__ float g_expsum[NNODES];
__device__ float g_lpg[Gn];
__device__ float g_selsum[Gn];

// smem byte offsets for k_edge (total 134144)
#define SM_PU    0
#define SM_PVB   512
#define SM_PW2   1024
#define SM_S1    1536
#define SM_S2    2048
#define SM_WH    3072
#define SM_A0    101376
#define SM_A1    117760
#define SM_TOTAL 134144

__device__ __forceinline__ uint32_t smem_u32(const void* p) {
    uint32_t a;
    asm("{ .reg .u64 t; cvta.to.shared.u64 t, %1; cvt.u32.u64 %0, t; }" : "=r"(a) : "l"(p));
    return a;
}
#define LDMX4(r, a) \
    asm volatile("ldmatrix.sync.aligned.m8n8.x4.shared.b16 {%0,%1,%2,%3}, [%4];" \
        : "=r"((r)[0]), "=r"((r)[1]), "=r"((r)[2]), "=r"((r)[3]) : "r"(a))

__device__ __forceinline__ void mma_bf16(float* d, const uint32_t* a, const uint32_t* b) {
    asm volatile("mma.sync.aligned.m16n8k16.row.col.f32.bf16.bf16.f32 "
        "{%0,%1,%2,%3}, {%4,%5,%6,%7}, {%8,%9}, {%0,%1,%2,%3};"
        : "+f"(d[0]), "+f"(d[1]), "+f"(d[2]), "+f"(d[3])
        : "r"(a[0]), "r"(a[1]), "r"(a[2]), "r"(a[3]), "r"(b[0]), "r"(b[1]));
}
__device__ __forceinline__ uint32_t cvt_bf16x2(float hi, float lo) {
    uint32_t r;
    asm("cvt.rn.bf16x2.f32 %0, %1, %2;" : "=r"(r) : "f"(hi), "f"(lo));
    return r;
}
__device__ __forceinline__ float geluf(float x) {
    return 0.5f * x * (1.0f + erff(x * 0.70710678118654752440f));
}

// ---------------- init ----------------
__global__ void k_init() {
    int i = blockIdx.x * blockDim.x + threadIdx.x;
    if (i < NNODES) { g_tmax[i] = -INFINITY; g_expsum[i] = 0.0f; }
    if (i < Gn) { g_lpg[i] = 0.0f; g_selsum[i] = 0.0f; }
}

// ---------------- prep: W' = g.*W -> bf16 swizzled; u, vb ----------------
__global__ void k_prep(const float* __restrict__ bw1, const float* __restrict__ blng,
                       const float* __restrict__ blnb, const float* __restrict__ bb1) {
    int j = blockIdx.x;     // output 0..127
    int k = threadIdx.x;    // 0..383
    __shared__ float rs[12], rv[12];
    float wraw = bw1[k * Hn + j];
    float wv = blng[k] * wraw;
    float vv = blnb[k] * wraw;
    int chunk = k >> 6, kloc = k & 63;
    uint32_t off = (uint32_t)(chunk * 16384 + j * 128 + ((kloc * 2) ^ ((j & 7) << 4)));
    *(unsigned short*)((char*)g_Wsw + off) = __bfloat16_as_ushort(__float2bfloat16(wv));
    float uu = wv;
    #pragma unroll
    for (int o = 16; o; o >>= 1) {
        uu += __shfl_xor_sync(0xffffffffu, uu, o);
        vv += __shfl_xor_sync(0xffffffffu, vv, o);
    }
    if ((k & 31) == 0) { rs[k >> 5] = uu; rv[k >> 5] = vv; }
    __syncthreads();
    if (k == 0) {
        float U = 0.f, V = 0.f;
        for (int i = 0; i < 12; i++) { U += rs[i]; V += rv[i]; }
        g_u[j] = U;
        g_vb[j] = V + bb1[j];
    }
}

// ---------------- fused start-attention + context MLP + log_z ----------------
__device__ __forceinline__ float bsum128(float v, float* red) {
    #pragma unroll
    for (int o = 16; o; o >>= 1) v += __shfl_xor_sync(0xffffffffu, v, o);
    __syncthreads();
    if ((threadIdx.x & 31) == 0) red[threadIdx.x >> 5] = v;
    __syncthreads();
    return red[0] + red[1] + red[2] + red[3];
}
__global__ void k_sctx(const float* __restrict__ nodes, const float* __restrict__ qt,
                       const int* __restrict__ locals, const int* __restrict__ ptr,
                       const float* __restrict__ cw1, const float* __restrict__ cb1,
                       const float* __restrict__ cw2, const float* __restrict__ cb2,
                       const float* __restrict__ ln1g, const float* __restrict__ ln1b,
                       const float* __restrict__ zw1, const float* __restrict__ zb1,
                       const float* __restrict__ zw2, const float* __restrict__ zb2,
                       float* __restrict__ out) {
    int g = blockIdx.x, t = threadIdx.x;  // 128 threads
    __shared__ float red[4];
    __shared__ float sc[64], salpha[64];
    __shared__ int   sidx[64];
    __shared__ float xin[256];
    __shared__ float h1[128];
    __shared__ float xh[128];
    // --- start aggregation ---
    int s0 = ptr[g], s1e = ptr[g + 1];
    int n = s1e - s0; if (n > 64) n = 64; if (n < 0) n = 0;
    float qv = qt[g * Hn + t];
    for (int s = 0; s < n; s++) {
        int nd = locals[s0 + s];
        if (t == 0) sidx[s] = nd;
        float p = nodes[nd * Hn + t] * qv;
        #pragma unroll
        for (int o = 16; o; o >>= 1) p += __shfl_xor_sync(0xffffffffu, p, o);
        if ((t & 31) == 0) red[t >> 5] = p;
        __syncthreads();
        if (t == 0) sc[s] = (red[0] + red[1] + red[2] + red[3]) * 0.08838834764831843f;
        __syncthreads();
    }
    if (t == 0) {
        float m = -INFINITY;
        for (int s = 0; s < n; s++) m = fmaxf(m, sc[s]);
        float d = 0.0f;
        for (int s = 0; s < n; s++) { float e = expf(sc[s] - m); salpha[s] = e; d += e; }
        float inv = 1.0f / d;
        for (int s = 0; s < n; s++) salpha[s] *= inv;
    }
    __syncthreads();
    float acc = 0.0f;
    for (int s = 0; s < n; s++) acc += salpha[s] * nodes[sidx[s] * Hn + t];
    xin[t] = acc;
    xin[128 + t] = qv;
    __syncthreads();
    // --- ctx MLP (multi-accumulator for ILP) ---
    float a0 = 0.f, a1 = 0.f, a2 = 0.f, a3 = 0.f;
    #pragma unroll 8
    for (int k = 0; k < 256; k += 4) {
        a0 = fmaf(xin[k + 0], cw1[(k + 0) * Hn + t], a0);
        a1 = fmaf(xin[k + 1], cw1[(k + 1) * Hn + t], a1);
        a2 = fmaf(xin[k + 2], cw1[(k + 2) * Hn + t], a2);
        a3 = fmaf(xin[k + 3], cw1[(k + 3) * Hn + t], a3);
    }
    h1[t] = geluf(cb1[t] + (a0 + a1) + (a2 + a3));
    __syncthreads();
    a0 = 0.f; a1 = 0.f; a2 = 0.f; a3 = 0.f;
    #pragma unroll 8
    for (int k = 0; k < 128; k += 4) {
        a0 = fmaf(h1[k + 0], cw2[(k + 0) * Hn + t], a0);
        a1 = fmaf(h1[k + 1], cw2[(k + 1) * Hn + t], a1);
        a2 = fmaf(h1[k + 2], cw2[(k + 2) * Hn + t], a2);
        a3 = fmaf(h1[k + 3], cw2[(k + 3) * Hn + t], a3);
    }
    float c = cb2[t] + (a0 + a1) + (a2 + a3);
    float mean = bsum128(c, red) * (1.0f / 128.0f);
    float d = c - mean;
    float var = bsum128(d * d, red) * (1.0f / 128.0f);
    xh[t] = d * rsqrtf(var + EPS_LN) * ln1g[t] + ln1b[t];
    __syncthreads();
    a0 = 0.f; a1 = 0.f; a2 = 0.f; a3 = 0.f;
    #pragma unroll 8
    for (int k = 0; k < 128; k += 4) {
        a0 = fmaf(xh[k + 0], zw1[(k + 0) * Hn + t], a0);
        a1 = fmaf(xh[k + 1], zw1[(k + 1) * Hn + t], a1);
        a2 = fmaf(xh[k + 2], zw1[(k + 2) * Hn + t], a2);
        a3 = fmaf(xh[k + 3], zw1[(k + 3) * Hn + t], a3);
    }
    float p = geluf(zb1[t] + (a0 + a1) + (a2 + a3)) * zw2[t];
    float lz = bsum128(p, red);
    if (t == 0) out[g * 3 + 0] = lz + zb2[0];
}

// ---------------- edge logits: single-term bf16 GEMM via mma.sync ----------------
__global__ void __launch_bounds__(256, 1)
k_edge(const float* __restrict__ nodes, const float* __restrict__ qt,
       const float* __restrict__ et,
       const int* __restrict__ ebatch, const int* __restrict__ eidx,
       const float* __restrict__ bw2, const float* __restrict__ bb2) {
    extern __shared__ char smem[];
    uint32_t sb = smem_u32(smem);
    int t = threadIdx.x, w = t >> 5, lane = t & 31;
    int warp_m = w >> 2, warp_n = w & 3;
    int eg = t >> 4;           // 0..15: edge row group
    int kg = t & 15;           // k-segment within row
    int cb = kg * 8;           // byte col of this thread's 4 bf16

    // stage weights + params
    {
        uint4* dh = (uint4*)(smem + SM_WH);
        for (int i = t; i < 6144; i += 256) dh[i] = g_Wsw[i];
    }
    float* pu  = (float*)(smem + SM_PU);
    float* pvb = (float*)(smem + SM_PVB);
    float* pw2 = (float*)(smem + SM_PW2);
    float* s1  = (float*)(smem + SM_S1);
    float* s2  = (float*)(smem + SM_S2);
    if (t < 128) { pu[t] = g_u[t]; pvb[t] = g_vb[t]; pw2[t] = bw2[t]; }
    __syncthreads();
    float bias2 = bb2[0];

    for (int tile = blockIdx.x; tile < NTILES; tile += gridDim.x) {
        int e0 = tile * 128;
        float acc[4][4][4];
        #pragma unroll
        for (int a = 0; a < 4; a++)
            #pragma unroll
            for (int b = 0; b < 4; b++)
                #pragma unroll
                for (int d = 0; d < 4; d++) acc[a][b][d] = 0.0f;
        float lnS[8], lnQ[8];
        #pragma unroll
        for (int i = 0; i < 8; i++) { lnS[i] = 0.0f; lnQ[i] = 0.0f; }
        float4 gv[8];

        #define LOADCHUNK(c) do { \
            int part = (c) >> 1; \
            int fo = ((c) & 1) * 64 + kg * 4; \
            _Pragma("unroll") \
            for (int i = 0; i < 8; i++) { \
                int e = e0 + eg + i * 16; \
                float4 v = make_float4(0.f, 0.f, 0.f, 0.f); \
                if (e < NEDGES) { \
                    const float* src; \
                    if (part == 0)      src = et + (size_t)e * Hn + fo; \
                    else if (part == 1) src = qt + (size_t)ebatch[e] * Hn + fo; \
                    else                src = nodes + (size_t)eidx[NEDGES + e] * Hn + fo; \
                    v = *(const float4*)src; \
                } \
                gv[i] = v; \
            } } while (0)

        #define CONV(buf) do { \
            _Pragma("unroll") \
            for (int i = 0; i < 8; i++) { \
                float4 v = gv[i]; int el = eg + i * 16; \
                lnS[i] += (v.x + v.y) + (v.z + v.w); \
                lnQ[i] += fmaf(v.x, v.x, fmaf(v.y, v.y, fmaf(v.z, v.z, v.w * v.w))); \
                uint2 H; \
                H.x = cvt_bf16x2(v.y, v.x); \
                H.y = cvt_bf16x2(v.w, v.z); \
                uint32_t off = (uint32_t)(el * 128 + (cb ^ ((el & 7) << 4))); \
                *(uint2*)(smem + (buf) + off) = H; \
            } } while (0)

        LOADCHUNK(0);
        #pragma unroll 1
        for (int c = 0; c < 6; c++) {
            int abuf = SM_A0 + (c & 1) * 16384;
            CONV(abuf);
            __syncthreads();
            if (c < 5) {
                switch (c) {
                    case 0: LOADCHUNK(1); break;
                    case 1: LOADCHUNK(2); break;
                    case 2: LOADCHUNK(3); break;
                    case 3: LOADCHUNK(4); break;
                    case 4: LOADCHUNK(5); break;
                }
            }
            uint32_t whc = sb + SM_WH + c * 16384;
            uint32_t abb = sb + (uint32_t)abuf;
            #pragma unroll
            for (int ks = 0; ks < 4; ks++) {
                int k0b = ks * 32;
                uint32_t ah[4][4], bh[8];
                #pragma unroll
                for (int mt = 0; mt < 4; mt++) {
                    int row = warp_m * 64 + mt * 16 + (lane & 7) + ((lane >> 3) & 1) * 8;
                    int colb = k0b + (lane >> 4) * 16;
                    uint32_t off = (uint32_t)(row * 128 + (colb ^ ((row & 7) << 4)));
                    LDMX4(ah[mt], abb + off);
                }
                #pragma unroll
                for (int bt = 0; bt < 2; bt++) {
                    int j = warp_n * 32 + bt * 16 + (lane & 7) + (lane >> 4) * 8;
                    int kb = k0b + ((lane >> 3) & 1) * 16;
                    uint32_t off = (uint32_t)(j * 128 + (kb ^ ((j & 7) << 4)));
                    LDMX4(&bh[bt * 4], whc + off);
                }
                #pragma unroll
                for (int mt = 0; mt < 4; mt++)
                    #pragma unroll
                    for (int nt = 0; nt < 4; nt++)
                        mma_bf16(acc[mt][nt], ah[mt], &bh[(nt >> 1) * 4 + (nt & 1) * 2]);
            }
        }
        #undef LOADCHUNK
        #undef CONV

        // LN stat totals -> smem
        #pragma unroll
        for (int i = 0; i < 8; i++) {
            float a = lnS[i], b = lnQ[i];
            #pragma unroll
            for (int o = 8; o; o >>= 1) {
                a += __shfl_xor_sync(0xffffffffu, a, o);
                b += __shfl_xor_sync(0xffffffffu, b, o);
            }
            if (kg == 0) { s1[eg + i * 16] = a; s2[eg + i * 16] = b; }
        }
        __syncthreads();

        // epilogue: folded LN + GELU + dot(w2)
        int g = lane >> 2, cpair = (lane & 3) * 2;
        float* spart = (float*)(smem + SM_A0);   // A0 is dead (last MMA used A1)
        #pragma unroll
        for (int mt = 0; mt < 4; mt++) {
            #pragma unroll
            for (int half = 0; half < 2; half++) {
                int row = warp_m * 64 + mt * 16 + half * 8 + g;
                float m  = s1[row] * (1.0f / 384.0f);
                float var = s2[row] * (1.0f / 384.0f) - m * m;
                float is = rsqrtf(fmaxf(var, 0.0f) + EPS_LN);
                float pv = 0.0f;
                #pragma unroll
                for (int nt = 0; nt < 4; nt++) {
                    int j0 = warp_n * 32 + nt * 8 + cpair;
                    float d0 = acc[mt][nt][half * 2 + 0];
                    float d1 = acc[mt][nt][half * 2 + 1];
                    float y0 = (d0 - m * pu[j0])     * is + pvb[j0];
                    float y1 = (d1 - m * pu[j0 + 1]) * is + pvb[j0 + 1];
                    pv = fmaf(geluf(y0), pw2[j0], pv);
                    pv = fmaf(geluf(y1), pw2[j0 + 1], pv);
                }
                pv += __shfl_xor_sync(0xffffffffu, pv, 1);
                pv += __shfl_xor_sync(0xffffffffu, pv, 2);
                if ((lane & 3) == 0) spart[warp_n * 128 + row] = pv;
            }
        }
        __syncthreads();
        if (t < 128) {
            int e = e0 + t;
            if (e < NEDGES)
                g_logits[e] = spart[t] + spart[128 + t] + spart[256 + t] + spart[384 + t] + bias2;
        }
        __syncthreads();
    }
}

// ---------------- segment softmax + per-graph sums ----------------
__global__ void k_smax(const int* __restrict__ eidx) {
    int e = blockIdx.x * blockDim.x + threadIdx.x;
    if (e >= NEDGES) return;
    int tg = eidx[NEDGES + e];
    float v = g_logits[e];
    if (v >= 0.0f) atomicMax((int*)&g_tmax[tg], __float_as_int(v));
    else           atomicMin((unsigned int*)&g_tmax[tg], __float_as_uint(v));
}
__global__ void k_sexp(const int* __restrict__ eidx) {
    int e = blockIdx.x * blockDim.x + threadIdx.x;
    if (e >= NEDGES) return;
    int tg = eidx[NEDGES + e];
    atomicAdd(&g_expsum[tg], expf(g_logits[e] - g_tmax[tg]));
}
__global__ void k_lpb(const int* __restrict__ eidx, const int* __restrict__ ebatch,
                      const int* __restrict__ mask) {
    const int CH = 16;
    int base = (blockIdx.x * blockDim.x + threadIdx.x) * CH;
    if (base >= NEDGES) return;
    int end = base + CH; if (end > NEDGES) end = NEDGES;
    int cur = -1; float aL = 0.0f, aS = 0.0f;
    for (int e = base; e < end; e++) {
        int b = ebatch[e];
        if (b != cur) {
            if (cur >= 0 && (aL != 0.0f || aS != 0.0f)) {
                atomicAdd(&g_lpg[cur], aL);
                atomicAdd(&g_selsum[cur], aS);
            }
            cur = b; aL = 0.0f; aS = 0.0f;
        }
        if (mask[e] != 0) {
            int tg = eidx[NEDGES + e];
            float lp = (g_logits[e] - g_tmax[tg]) - logf(g_expsum[tg]);
            aL += lp; aS += 1.0f;
        }
    }
    if (cur >= 0 && (aL != 0.0f || aS != 0.0f)) {
        atomicAdd(&g_lpg[cur], aL);
        atomicAdd(&g_selsum[cur], aS);
    }
}
__global__ void k_fin(float* __restrict__ out) {
    int g = threadIdx.x;
    __shared__ float rs[32], rc[32];
    __shared__ float s_res;
    float lpg = g_lpg[g];
    float has = (g_selsum[g] > 0.0f) ? 1.0f : 0.0f;
    float v1 = -lpg * has, v2 = has;
    #pragma unroll
    for (int o = 16; o; o >>= 1) {
        v1 += __shfl_xor_sync(0xffffffffu, v1, o);
        v2 += __shfl_xor_sync(0xffffffffu, v2, o);
    }
    if ((g & 31) == 0) { rs[g >> 5] = v1; rc[g >> 5] = v2; }
    __syncthreads();
    if (g < 32) {
        float a = rs[g], b = rc[g];
        #pragma unroll
        for (int o = 16; o; o >>= 1) {
            a += __shfl_xor_sync(0xffffffffu, a, o);
            b += __shfl_xor_sync(0xffffffffu, b, o);
        }
        if (g == 0) s_res = a / fmaxf(b, 1.0f);
    }
    __syncthreads();
    out[g * 3 + 1] = lpg;
    out[g * 3 + 2] = s_res;
}

// ---------------- host ----------------
extern "C" void kernel_launch(void* const* d_in, const int* in_sizes, int n_in,
                              void* d_out, int out_size) {
    int I_node, I_q, I_edge, I_loc, I_ptr, I_eb, I_mask, I_eidx;
    int I_ln1g, I_ln1b, I_zw1, I_zb1, I_zw2, I_zb2;
    int I_cw1, I_cb1, I_cw2, I_cb2, I_blng, I_blnb, I_bw1, I_bb1, I_bw2, I_bb2;
    if (in_sizes[3] == 4096) {  // dict order
        I_node = 0; I_q = 1; I_edge = 2; I_loc = 3; I_ptr = 4; I_eb = 5; I_mask = 6; I_eidx = 7;
        I_ln1g = 8; I_ln1b = 9; I_zw1 = 10; I_zb1 = 11; I_zw2 = 12; I_zb2 = 13;
        I_cw1 = 14; I_cb1 = 15; I_cw2 = 16; I_cb2 = 17;
        I_blng = 18; I_blnb = 19; I_bw1 = 20; I_bb1 = 21; I_bw2 = 22; I_bb2 = 23;
    } else {                    // signature order
        I_node = 0; I_q = 1; I_edge = 2;
        I_ln1g = 3; I_ln1b = 4; I_zw1 = 5; I_zb1 = 6; I_zw2 = 7; I_zb2 = 8;
        I_cw1 = 9; I_cb1 = 10; I_cw2 = 11; I_cb2 = 12;
        I_blng = 13; I_blnb = 14; I_bw1 = 15; I_bb1 = 16; I_bw2 = 17; I_bb2 = 18;
        I_loc = 19; I_ptr = 20; I_eb = 21; I_mask = 22; I_eidx = 23;
    }

    const float* nodes = (const float*)d_in[I_node];
    const float* qt    = (const float*)d_in[I_q];
    const float* et    = (const float*)d_in[I_edge];
    const int*   locs  = (const int*)d_in[I_loc];
    const int*   ptr   = (const int*)d_in[I_ptr];
    const int*   ebat  = (const int*)d_in[I_eb];
    const int*   mask  = (const int*)d_in[I_mask];
    const int*   eidx  = (const int*)d_in[I_eidx];
    float* out = (float*)d_out;

    int dev = 0, nsm = 148;
    cudaGetDevice(&dev);
    cudaDeviceGetAttribute(&nsm, cudaDevAttrMultiProcessorCount, dev);

    static int smem_set = 0;
    if (!smem_set) {
        cudaFuncSetAttribute(k_edge, cudaFuncAttributeMaxDynamicSharedMemorySize, SM_TOTAL);
        smem_set = 1;
    }

    k_init<<<(NNODES + 255) / 256, 256>>>();
    k_prep<<<128, 384>>>((const float*)d_in[I_bw1], (const float*)d_in[I_blng],
                         (const float*)d_in[I_blnb], (const float*)d_in[I_bb1]);
    k_sctx<<<Gn, 128>>>(nodes, qt, locs, ptr,
                        (const float*)d_in[I_cw1], (const float*)d_in[I_cb1],
                        (const float*)d_in[I_cw2], (const float*)d_in[I_cb2],
                        (const float*)d_in[I_ln1g], (const float*)d_in[I_ln1b],
                        (const float*)d_in[I_zw1], (const float*)d_in[I_zb1],
                        (const float*)d_in[I_zw2], (const float*)d_in[I_zb2],
                        out);
    k_edge<<<nsm, 256, SM_TOTAL>>>(nodes, qt, et, ebat, eidx,
                                   (const float*)d_in[I_bw2], (const float*)d_in[I_bb2]);
    k_smax<<<(NEDGES + 255) / 256, 256>>>(eidx);
    k_sexp<<<(NEDGES + 255) / 256, 256>>>(eidx);
    k_lpb<<<((NEDGES + 15) / 16 + 255) / 256, 256>>>(eidx, ebat, mask);
    k_fin<<<1, 1024>>>(out);
}

// round 6
// speedup vs baseline: 7.2190x; 1.4608x over previous
#include <cuda_runtime.h>
#include <cuda_bf16.h>
#include <math.h>
#include <stdint.h>

#define Gn 1024
#define Hn 128
#define NNODES 100000
#define NEDGES 500000
#define EPS_LN 1e-5f
#define TILE 256
#define NT2 ((NEDGES + TILE - 1) / TILE)

// ---------------- device scratch ----------------
__device__ float g_u[Hn];
__device__ float g_vb[Hn];
__device__ uint4 g_Wsw[6144];          // 96KB bf16 W', [chunk][j][64k], XOR-16B swizzle
__device__ uint2 g_nbf[NNODES * 32];   // bf16 node tokens (25.6MB)
__device__ uint2 g_ebf[NEDGES * 32];   // bf16 edge tokens (128MB)
__device__ uint2 g_qbf[Gn * 32];       // bf16 question tokens
__device__ float2 g_nstat[NNODES];     // per-row (sum, sumsq)
__device__ float2 g_estat[NEDGES];
__device__ float2 g_qstat[Gn];
__device__ float g_logits[NEDGES];
__device__ float g_tmax[NNODES];
__device__ float g_expsum[NNODES];
__device__ float g_lpg[Gn];
__device__ float g_selsum[Gn];

// smem byte offsets for k_edge (total 169984)
#define SM_PU    0
#define SM_PVB   512
#define SM_PW2   1024
#define SM_STAT  1536     // 256 x float2
#define SM_SPART 3584     // 512 x float
#define SM_WH    6144     // 96KB weights
#define SM_A0    104448   // 32KB A buf 0 (256 rows x 128B)
#define SM_A1    137216   // 32KB A buf 1
#define SM_TOTAL 169984

__device__ __forceinline__ uint32_t smem_u32(const void* p) {
    uint32_t a;
    asm("{ .reg .u64 t; cvta.to.shared.u64 t, %1; cvt.u32.u64 %0, t; }" : "=r"(a) : "l"(p));
    return a;
}
#define LDMX4(r, a) \
    asm volatile("ldmatrix.sync.aligned.m8n8.x4.shared.b16 {%0,%1,%2,%3}, [%4];" \
        : "=r"((r)[0]), "=r"((r)[1]), "=r"((r)[2]), "=r"((r)[3]) : "r"(a))
#define CP16(dst, src) \
    asm volatile("cp.async.cg.shared.global [%0], [%1], 16;" :: "r"(dst), "l"(src))
#define CP_COMMIT() asm volatile("cp.async.commit_group;" ::: "memory")

__device__ __forceinline__ void mma_bf16(float* d, const uint32_t* a, const uint32_t* b) {
    asm volatile("mma.sync.aligned.m16n8k16.row.col.f32.bf16.bf16.f32 "
        "{%0,%1,%2,%3}, {%4,%5,%6,%7}, {%8,%9}, {%0,%1,%2,%3};"
        : "+f"(d[0]), "+f"(d[1]), "+f"(d[2]), "+f"(d[3])
        : "r"(a[0]), "r"(a[1]), "r"(a[2]), "r"(a[3]), "r"(b[0]), "r"(b[1]));
}
__device__ __forceinline__ uint32_t cvt_bf16x2(float hi, float lo) {
    uint32_t r;
    asm("cvt.rn.bf16x2.f32 %0, %1, %2;" : "=r"(r) : "f"(hi), "f"(lo));
    return r;
}
__device__ __forceinline__ float geluf(float x) {
    return 0.5f * x * (1.0f + erff(x * 0.70710678118654752440f));
}

// ---------------- init ----------------
__global__ void k_init() {
    int i = blockIdx.x * blockDim.x + threadIdx.x;
    if (i < NNODES) { g_tmax[i] = -INFINITY; g_expsum[i] = 0.0f; }
    if (i < Gn) { g_lpg[i] = 0.0f; g_selsum[i] = 0.0f; }
}

// ---------------- convert fp32 tokens -> bf16 + per-row LN partial sums ----------------
__global__ void k_cvt(const float4* __restrict__ src, uint2* __restrict__ dst,
                      float2* __restrict__ stat, int nrows) {
    int wid = (blockIdx.x * blockDim.x + threadIdx.x) >> 5;
    int lane = threadIdx.x & 31;
    if (wid >= nrows) return;
    float4 v = src[(size_t)wid * 32 + lane];
    uint2 o;
    o.x = cvt_bf16x2(v.y, v.x);
    o.y = cvt_bf16x2(v.w, v.z);
    dst[(size_t)wid * 32 + lane] = o;
    float s = (v.x + v.y) + (v.z + v.w);
    float q = fmaf(v.x, v.x, fmaf(v.y, v.y, fmaf(v.z, v.z, v.w * v.w)));
    #pragma unroll
    for (int off = 16; off; off >>= 1) {
        s += __shfl_xor_sync(0xffffffffu, s, off);
        q += __shfl_xor_sync(0xffffffffu, q, off);
    }
    if (lane == 0) stat[wid] = make_float2(s, q);
}

// ---------------- prep: W' = g.*W -> bf16 swizzled; u, vb ----------------
__global__ void k_prep(const float* __restrict__ bw1, const float* __restrict__ blng,
                       const float* __restrict__ blnb, const float* __restrict__ bb1) {
    int j = blockIdx.x;     // output 0..127
    int k = threadIdx.x;    // 0..383
    __shared__ float rs[12], rv[12];
    float wraw = bw1[k * Hn + j];
    float wv = blng[k] * wraw;
    float vv = blnb[k] * wraw;
    int chunk = k >> 6, kloc = k & 63;
    uint32_t off = (uint32_t)(chunk * 16384 + j * 128 + ((kloc * 2) ^ ((j & 7) << 4)));
    *(unsigned short*)((char*)g_Wsw + off) = __bfloat16_as_ushort(__float2bfloat16(wv));
    float uu = wv;
    #pragma unroll
    for (int o = 16; o; o >>= 1) {
        uu += __shfl_xor_sync(0xffffffffu, uu, o);
        vv += __shfl_xor_sync(0xffffffffu, vv, o);
    }
    if ((k & 31) == 0) { rs[k >> 5] = uu; rv[k >> 5] = vv; }
    __syncthreads();
    if (k == 0) {
        float U = 0.f, V = 0.f;
        for (int i = 0; i < 12; i++) { U += rs[i]; V += rv[i]; }
        g_u[j] = U;
        g_vb[j] = V + bb1[j];
    }
}

// ---------------- fused start-attention + context MLP + log_z ----------------
__device__ __forceinline__ float bsum128(float v, float* red) {
    #pragma unroll
    for (int o = 16; o; o >>= 1) v += __shfl_xor_sync(0xffffffffu, v, o);
    __syncthreads();
    if ((threadIdx.x & 31) == 0) red[threadIdx.x >> 5] = v;
    __syncthreads();
    return red[0] + red[1] + red[2] + red[3];
}
__global__ void k_sctx(const float* __restrict__ nodes, const float* __restrict__ qt,
                       const int* __restrict__ locals, const int* __restrict__ ptr,
                       const float* __restrict__ cw1, const float* __restrict__ cb1,
                       const float* __restrict__ cw2, const float* __restrict__ cb2,
                       const float* __restrict__ ln1g, const float* __restrict__ ln1b,
                       const float* __restrict__ zw1, const float* __restrict__ zb1,
                       const float* __restrict__ zw2, const float* __restrict__ zb2,
                       float* __restrict__ out) {
    int g = blockIdx.x, t = threadIdx.x;  // 128 threads
    __shared__ float red[4];
    __shared__ float sc[64], salpha[64];
    __shared__ int   sidx[64];
    __shared__ float xin[256];
    __shared__ float h1[128];
    __shared__ float xh[128];
    int s0 = ptr[g], s1e = ptr[g + 1];
    int n = s1e - s0; if (n > 64) n = 64; if (n < 0) n = 0;
    float qv = qt[g * Hn + t];
    for (int s = 0; s < n; s++) {
        int nd = locals[s0 + s];
        if (t == 0) sidx[s] = nd;
        float p = nodes[nd * Hn + t] * qv;
        #pragma unroll
        for (int o = 16; o; o >>= 1) p += __shfl_xor_sync(0xffffffffu, p, o);
        if ((t & 31) == 0) red[t >> 5] = p;
        __syncthreads();
        if (t == 0) sc[s] = (red[0] + red[1] + red[2] + red[3]) * 0.08838834764831843f;
        __syncthreads();
    }
    if (t == 0) {
        float m = -INFINITY;
        for (int s = 0; s < n; s++) m = fmaxf(m, sc[s]);
        float d = 0.0f;
        for (int s = 0; s < n; s++) { float e = expf(sc[s] - m); salpha[s] = e; d += e; }
        float inv = 1.0f / d;
        for (int s = 0; s < n; s++) salpha[s] *= inv;
    }
    __syncthreads();
    float acc = 0.0f;
    for (int s = 0; s < n; s++) acc += salpha[s] * nodes[sidx[s] * Hn + t];
    xin[t] = acc;
    xin[128 + t] = qv;
    __syncthreads();
    float a0 = 0.f, a1 = 0.f, a2 = 0.f, a3 = 0.f;
    #pragma unroll 8
    for (int k = 0; k < 256; k += 4) {
        a0 = fmaf(xin[k + 0], cw1[(k + 0) * Hn + t], a0);
        a1 = fmaf(xin[k + 1], cw1[(k + 1) * Hn + t], a1);
        a2 = fmaf(xin[k + 2], cw1[(k + 2) * Hn + t], a2);
        a3 = fmaf(xin[k + 3], cw1[(k + 3) * Hn + t], a3);
    }
    h1[t] = geluf(cb1[t] + (a0 + a1) + (a2 + a3));
    __syncthreads();
    a0 = 0.f; a1 = 0.f; a2 = 0.f; a3 = 0.f;
    #pragma unroll 8
    for (int k = 0; k < 128; k += 4) {
        a0 = fmaf(h1[k + 0], cw2[(k + 0) * Hn + t], a0);
        a1 = fmaf(h1[k + 1], cw2[(k + 1) * Hn + t], a1);
        a2 = fmaf(h1[k + 2], cw2[(k + 2) * Hn + t], a2);
        a3 = fmaf(h1[k + 3], cw2[(k + 3) * Hn + t], a3);
    }
    float c = cb2[t] + (a0 + a1) + (a2 + a3);
    float mean = bsum128(c, red) * (1.0f / 128.0f);
    float d = c - mean;
    float var = bsum128(d * d, red) * (1.0f / 128.0f);
    xh[t] = d * rsqrtf(var + EPS_LN) * ln1g[t] + ln1b[t];
    __syncthreads();
    a0 = 0.f; a1 = 0.f; a2 = 0.f; a3 = 0.f;
    #pragma unroll 8
    for (int k = 0; k < 128; k += 4) {
        a0 = fmaf(xh[k + 0], zw1[(k + 0) * Hn + t], a0);
        a1 = fmaf(xh[k + 1], zw1[(k + 1) * Hn + t], a1);
        a2 = fmaf(xh[k + 2], zw1[(k + 2) * Hn + t], a2);
        a3 = fmaf(xh[k + 3], zw1[(k + 3) * Hn + t], a3);
    }
    float p = geluf(zb1[t] + (a0 + a1) + (a2 + a3)) * zw2[t];
    float lz = bsum128(p, red);
    if (t == 0) out[g * 3 + 0] = lz + zb2[0];
}

// ---------------- edge logits: bf16 GEMM, cp.async gather, 512 threads ----------------
__global__ void __launch_bounds__(512, 1)
k_edge(const int* __restrict__ ebatch, const int* __restrict__ eidx,
       const float* __restrict__ bw2, const float* __restrict__ bb2) {
    extern __shared__ char smem[];
    uint32_t sb = smem_u32(smem);
    int t = threadIdx.x, lane = t & 31;
    int w = t >> 5;
    int warp_m = w >> 1, warp_n = w & 1;

    // stage weights + params
    {
        uint4* dh = (uint4*)(smem + SM_WH);
        for (int i = t; i < 6144; i += 512) dh[i] = g_Wsw[i];
    }
    float* pu  = (float*)(smem + SM_PU);
    float* pvb = (float*)(smem + SM_PVB);
    float* pw2 = (float*)(smem + SM_PW2);
    float2* st = (float2*)(smem + SM_STAT);
    float* spart = (float*)(smem + SM_SPART);
    if (t < 128) { pu[t] = g_u[t]; pvb[t] = g_vb[t]; pw2[t] = bw2[t]; }
    __syncthreads();
    float bias2 = bb2[0];

    int r = t >> 1;                 // my gather row (0..255), 2 threads per row
    int segbase = (t & 1) * 4;      // 4 x 16B per thread per chunk
    uint32_t swrow = (uint32_t)((r & 7) << 4);
    uint32_t dst0 = sb + SM_A0 + r * 128;
    uint32_t dst1 = sb + SM_A1 + r * 128;

    for (int tile = blockIdx.x; tile < NT2; tile += gridDim.x) {
        int e0 = tile * TILE;
        int e = e0 + r; if (e >= NEDGES) e = NEDGES - 1;
        int br = ebatch[e], tgr = eidx[NEDGES + e];
        const char* srcE = (const char*)(g_ebf + (size_t)e * 32);
        const char* srcQ = (const char*)(g_qbf + (size_t)br * 32);
        const char* srcN = (const char*)(g_nbf + (size_t)tgr * 32);

        // issue chunk 0 (edge tokens, first 64 k)
        #pragma unroll
        for (int i = 0; i < 4; i++) {
            int sg = segbase + i;
            CP16(dst0 + ((sg * 16) ^ swrow), srcE + sg * 16);
        }
        CP_COMMIT();

        // per-edge LN stats = sum of 3 per-row partials
        if (t < 256) {
            int e2 = e0 + t; if (e2 >= NEDGES) e2 = NEDGES - 1;
            int b2 = ebatch[e2], tg2 = eidx[NEDGES + e2];
            float2 a = g_estat[e2];
            float2 bq = g_qstat[b2];
            float2 cn = g_nstat[tg2];
            st[t] = make_float2(a.x + bq.x + cn.x, a.y + bq.y + cn.y);
        }

        float acc[2][8][4];
        #pragma unroll
        for (int a = 0; a < 2; a++)
            #pragma unroll
            for (int b = 0; b < 8; b++)
                #pragma unroll
                for (int d = 0; d < 4; d++) acc[a][b][d] = 0.0f;

        #pragma unroll 1
        for (int c = 0; c < 6; c++) {
            if (c < 5) {
                int cn = c + 1;
                int part = cn >> 1, half = cn & 1;
                const char* srcp = (part == 0) ? srcE : ((part == 1) ? srcQ : srcN);
                uint32_t dst = (cn & 1) ? dst1 : dst0;
                #pragma unroll
                for (int i = 0; i < 4; i++) {
                    int sg = segbase + i;
                    CP16(dst + ((sg * 16) ^ swrow), srcp + half * 128 + sg * 16);
                }
                CP_COMMIT();
                asm volatile("cp.async.wait_group 1;" ::: "memory");
            } else {
                asm volatile("cp.async.wait_group 0;" ::: "memory");
            }
            __syncthreads();
            uint32_t whc = sb + SM_WH + c * 16384;
            uint32_t abb = sb + ((c & 1) ? SM_A1 : SM_A0);
            #pragma unroll
            for (int ks = 0; ks < 4; ks++) {
                uint32_t ah[2][4], bh[16];
                #pragma unroll
                for (int mt = 0; mt < 2; mt++) {
                    int row = warp_m * 32 + mt * 16 + (lane & 7) + ((lane >> 3) & 1) * 8;
                    int colb = ks * 32 + (lane >> 4) * 16;
                    LDMX4(ah[mt], abb + (uint32_t)(row * 128 + (colb ^ ((row & 7) << 4))));
                }
                #pragma unroll
                for (int bt = 0; bt < 4; bt++) {
                    int j = warp_n * 64 + bt * 16 + (lane & 7) + (lane >> 4) * 8;
                    int kb = ks * 32 + ((lane >> 3) & 1) * 16;
                    LDMX4(&bh[bt * 4], whc + (uint32_t)(j * 128 + (kb ^ ((j & 7) << 4))));
                }
                #pragma unroll
                for (int mt = 0; mt < 2; mt++)
                    #pragma unroll
                    for (int nt = 0; nt < 8; nt++)
                        mma_bf16(acc[mt][nt], ah[mt], &bh[(nt >> 1) * 4 + (nt & 1) * 2]);
            }
            __syncthreads();
        }

        // epilogue: folded LN + GELU + dot(w2)
        int gq = lane >> 2, cpair = (lane & 3) * 2;
        #pragma unroll
        for (int mt = 0; mt < 2; mt++) {
            #pragma unroll
            for (int half = 0; half < 2; half++) {
                int row = warp_m * 32 + mt * 16 + half * 8 + gq;
                float2 sv = st[row];
                float m = sv.x * (1.0f / 384.0f);
                float var = sv.y * (1.0f / 384.0f) - m * m;
                float is = rsqrtf(fmaxf(var, 0.0f) + EPS_LN);
                float pv = 0.0f;
                #pragma unroll
                for (int nt = 0; nt < 8; nt++) {
                    int j0 = warp_n * 64 + nt * 8 + cpair;
                    float d0 = acc[mt][nt][half * 2 + 0];
                    float d1 = acc[mt][nt][half * 2 + 1];
                    float y0 = (d0 - m * pu[j0])     * is + pvb[j0];
                    float y1 = (d1 - m * pu[j0 + 1]) * is + pvb[j0 + 1];
                    pv = fmaf(geluf(y0), pw2[j0], pv);
                    pv = fmaf(geluf(y1), pw2[j0 + 1], pv);
                }
                pv += __shfl_xor_sync(0xffffffffu, pv, 1);
                pv += __shfl_xor_sync(0xffffffffu, pv, 2);
                if ((lane & 3) == 0) spart[warp_n * 256 + row] = pv;
            }
        }
        __syncthreads();
        if (t < 256) {
            int e2 = e0 + t;
            if (e2 < NEDGES) g_logits[e2] = spart[t] + spart[256 + t] + bias2;
        }
        __syncthreads();
    }
}

// ---------------- segment softmax + per-graph sums ----------------
__global__ void k_smax(const int* __restrict__ eidx) {
    int e = blockIdx.x * blockDim.x + threadIdx.x;
    if (e >= NEDGES) return;
    int tg = eidx[NEDGES + e];
    float v = g_logits[e];
    if (v >= 0.0f) atomicMax((int*)&g_tmax[tg], __float_as_int(v));
    else           atomicMin((unsigned int*)&g_tmax[tg], __float_as_uint(v));
}
__global__ void k_sexp(const int* __restrict__ eidx) {
    int e = blockIdx.x * blockDim.x + threadIdx.x;
    if (e >= NEDGES) return;
    int tg = eidx[NEDGES + e];
    atomicAdd(&g_expsum[tg], expf(g_logits[e] - g_tmax[tg]));
}
__global__ void k_lpb(const int* __restrict__ eidx, const int* __restrict__ ebatch,
                      const int* __restrict__ mask) {
    const int CH = 16;
    int base = (blockIdx.x * blockDim.x + threadIdx.x) * CH;
    if (base >= NEDGES) return;
    int end = base + CH; if (end > NEDGES) end = NEDGES;
    int cur = -1; float aL = 0.0f, aS = 0.0f;
    for (int e = base; e < end; e++) {
        int b = ebatch[e];
        if (b != cur) {
            if (cur >= 0 && (aL != 0.0f || aS != 0.0f)) {
                atomicAdd(&g_lpg[cur], aL);
                atomicAdd(&g_selsum[cur], aS);
            }
            cur = b; aL = 0.0f; aS = 0.0f;
        }
        if (mask[e] != 0) {
            int tg = eidx[NEDGES + e];
            float lp = (g_logits[e] - g_tmax[tg]) - logf(g_expsum[tg]);
            aL += lp; aS += 1.0f;
        }
    }
    if (cur >= 0 && (aL != 0.0f || aS != 0.0f)) {
        atomicAdd(&g_lpg[cur], aL);
        atomicAdd(&g_selsum[cur], aS);
    }
}
__global__ void k_fin(float* __restrict__ out) {
    int g = threadIdx.x;
    __shared__ float rs[32], rc[32];
    __shared__ float s_res;
    float lpg = g_lpg[g];
    float has = (g_selsum[g] > 0.0f) ? 1.0f : 0.0f;
    float v1 = -lpg * has, v2 = has;
    #pragma unroll
    for (int o = 16; o; o >>= 1) {
        v1 += __shfl_xor_sync(0xffffffffu, v1, o);
        v2 += __shfl_xor_sync(0xffffffffu, v2, o);
    }
    if ((g & 31) == 0) { rs[g >> 5] = v1; rc[g >> 5] = v2; }
    __syncthreads();
    if (g < 32) {
        float a = rs[g], b = rc[g];
        #pragma unroll
        for (int o = 16; o; o >>= 1) {
            a += __shfl_xor_sync(0xffffffffu, a, o);
            b += __shfl_xor_sync(0xffffffffu, b, o);
        }
        if (g == 0) s_res = a / fmaxf(b, 1.0f);
    }
    __syncthreads();
    out[g * 3 + 1] = lpg;
    out[g * 3 + 2] = s_res;
}

// ---------------- host ----------------
extern "C" void kernel_launch(void* const* d_in, const int* in_sizes, int n_in,
                              void* d_out, int out_size) {
    int I_node, I_q, I_edge, I_loc, I_ptr, I_eb, I_mask, I_eidx;
    int I_ln1g, I_ln1b, I_zw1, I_zb1, I_zw2, I_zb2;
    int I_cw1, I_cb1, I_cw2, I_cb2, I_blng, I_blnb, I_bw1, I_bb1, I_bw2, I_bb2;
    if (in_sizes[3] == 4096) {  // dict order
        I_node = 0; I_q = 1; I_edge = 2; I_loc = 3; I_ptr = 4; I_eb = 5; I_mask = 6; I_eidx = 7;
        I_ln1g = 8; I_ln1b = 9; I_zw1 = 10; I_zb1 = 11; I_zw2 = 12; I_zb2 = 13;
        I_cw1 = 14; I_cb1 = 15; I_cw2 = 16; I_cb2 = 17;
        I_blng = 18; I_blnb = 19; I_bw1 = 20; I_bb1 = 21; I_bw2 = 22; I_bb2 = 23;
    } else {                    // signature order
        I_node = 0; I_q = 1; I_edge = 2;
        I_ln1g = 3; I_ln1b = 4; I_zw1 = 5; I_zb1 = 6; I_zw2 = 7; I_zb2 = 8;
        I_cw1 = 9; I_cb1 = 10; I_cw2 = 11; I_cb2 = 12;
        I_blng = 13; I_blnb = 14; I_bw1 = 15; I_bb1 = 16; I_bw2 = 17; I_bb2 = 18;
        I_loc = 19; I_ptr = 20; I_eb = 21; I_mask = 22; I_eidx = 23;
    }

    const float* nodes = (const float*)d_in[I_node];
    const float* qt    = (const float*)d_in[I_q];
    const float* et    = (const float*)d_in[I_edge];
    const int*   locs  = (const int*)d_in[I_loc];
    const int*   ptr   = (const int*)d_in[I_ptr];
    const int*   ebat  = (const int*)d_in[I_eb];
    const int*   mask  = (const int*)d_in[I_mask];
    const int*   eidx  = (const int*)d_in[I_eidx];
    float* out = (float*)d_out;

    int dev = 0, nsm = 148;
    cudaGetDevice(&dev);
    cudaDeviceGetAttribute(&nsm, cudaDevAttrMultiProcessorCount, dev);

    static int smem_set = 0;
    if (!smem_set) {
        cudaFuncSetAttribute(k_edge, cudaFuncAttributeMaxDynamicSharedMemorySize, SM_TOTAL);
        smem_set = 1;
    }

    // resolve device scratch pointers for k_cvt outputs
    uint2* p_nbf; uint2* p_ebf; uint2* p_qbf;
    float2* p_nst; float2* p_est; float2* p_qst;
    cudaGetSymbolAddress((void**)&p_nbf, g_nbf);
    cudaGetSymbolAddress((void**)&p_ebf, g_ebf);
    cudaGetSymbolAddress((void**)&p_qbf, g_qbf);
    cudaGetSymbolAddress((void**)&p_nst, g_nstat);
    cudaGetSymbolAddress((void**)&p_est, g_estat);
    cudaGetSymbolAddress((void**)&p_qst, g_qstat);

    k_init<<<(NNODES + 255) / 256, 256>>>();
    k_prep<<<128, 384>>>((const float*)d_in[I_bw1], (const float*)d_in[I_blng],
                         (const float*)d_in[I_blnb], (const float*)d_in[I_bb1]);
    k_cvt<<<(NNODES + 7) / 8, 256>>>((const float4*)nodes, p_nbf, p_nst, NNODES);
    k_cvt<<<(NEDGES + 7) / 8, 256>>>((const float4*)et, p_ebf, p_est, NEDGES);
    k_cvt<<<(Gn + 7) / 8, 256>>>((const float4*)qt, p_qbf, p_qst, Gn);
    k_sctx<<<Gn, 128>>>(nodes, qt, locs, ptr,
                        (const float*)d_in[I_cw1], (const float*)d_in[I_cb1],
                        (const float*)d_in[I_cw2], (const float*)d_in[I_cb2],
                        (const float*)d_in[I_ln1g], (const float*)d_in[I_ln1b],
                        (const float*)d_in[I_zw1], (const float*)d_in[I_zb1],
                        (const float*)d_in[I_zw2], (const float*)d_in[I_zb2],
                        out);
    k_edge<<<nsm, 512, SM_TOTAL>>>(ebat, eidx,
                                   (const float*)d_in[I_bw2], (const float*)d_in[I_bb2]);
    k_smax<<<(NEDGES + 255) / 256, 256>>>(eidx);
    k_sexp<<<(NEDGES + 255) / 256, 256>>>(eidx);
    k_lpb<<<((NEDGES + 15) / 16 + 255) / 256, 256>>>(eidx, ebat, mask);
    k_fin<<<1, 1024>>>(out);
}

// round 7
// speedup vs baseline: 7.5509x; 1.0460x over previous
#include <cuda_runtime.h>
#include <cuda_bf16.h>
#include <math.h>
#include <stdint.h>

#define Gn 1024
#define Hn 128
#define NNODES 100000
#define NEDGES 500000
#define EPS_LN 1e-5f
#define TILE 256
#define NT2 ((NEDGES + TILE - 1) / TILE)

// ---------------- device scratch ----------------
__device__ float g_u[Hn];
__device__ float g_vb[Hn];
__device__ uint4 g_Wsw[6144];          // 96KB bf16 W', [chunk][j][64k], XOR-16B swizzle
__device__ uint2 g_nbf[NNODES * 32];   // bf16 node tokens (25.6MB)
__device__ uint2 g_qbf[Gn * 32];       // bf16 question tokens
__device__ float2 g_nstat[NNODES];     // per-row (sum, sumsq)
__device__ float2 g_qstat[Gn];
__device__ float g_logits[NEDGES];
__device__ float g_expsum[NNODES];
__device__ float g_lpg[Gn];
__device__ float g_selsum[Gn];

// smem byte offsets for k_edge (total 169984)
#define SM_PU    0
#define SM_PVB   512
#define SM_PW2   1024
#define SM_STAT  1536     // 256 x float2
#define SM_SPART 3584     // 512 x float
#define SM_WH    6144     // 96KB weights
#define SM_A0    104448   // 32KB A buf 0 (256 rows x 128B)
#define SM_A1    137216   // 32KB A buf 1
#define SM_TOTAL 169984

__device__ __forceinline__ uint32_t smem_u32(const void* p) {
    uint32_t a;
    asm("{ .reg .u64 t; cvta.to.shared.u64 t, %1; cvt.u32.u64 %0, t; }" : "=r"(a) : "l"(p));
    return a;
}
#define LDMX4(r, a) \
    asm volatile("ldmatrix.sync.aligned.m8n8.x4.shared.b16 {%0,%1,%2,%3}, [%4];" \
        : "=r"((r)[0]), "=r"((r)[1]), "=r"((r)[2]), "=r"((r)[3]) : "r"(a))
#define CP16(dst, src) \
    asm volatile("cp.async.cg.shared.global [%0], [%1], 16;" :: "r"(dst), "l"(src))
#define CP_COMMIT() asm volatile("cp.async.commit_group;" ::: "memory")

__device__ __forceinline__ void mma_bf16(float* d, const uint32_t* a, const uint32_t* b) {
    asm volatile("mma.sync.aligned.m16n8k16.row.col.f32.bf16.bf16.f32 "
        "{%0,%1,%2,%3}, {%4,%5,%6,%7}, {%8,%9}, {%0,%1,%2,%3};"
        : "+f"(d[0]), "+f"(d[1]), "+f"(d[2]), "+f"(d[3])
        : "r"(a[0]), "r"(a[1]), "r"(a[2]), "r"(a[3]), "r"(b[0]), "r"(b[1]));
}
__device__ __forceinline__ uint32_t cvt_bf16x2(float hi, float lo) {
    uint32_t r;
    asm("cvt.rn.bf16x2.f32 %0, %1, %2;" : "=r"(r) : "f"(hi), "f"(lo));
    return r;
}
__device__ __forceinline__ float geluf(float x) {
    return 0.5f * x * (1.0f + erff(x * 0.70710678118654752440f));
}

// ---------------- init ----------------
__global__ void k_init() {
    int i = blockIdx.x * blockDim.x + threadIdx.x;
    if (i < NNODES) g_expsum[i] = 0.0f;
    if (i < Gn) { g_lpg[i] = 0.0f; g_selsum[i] = 0.0f; }
}

// ---------------- convert fp32 tokens -> bf16 + per-row LN partial sums ----------------
__global__ void k_cvt(const float4* __restrict__ src, uint2* __restrict__ dst,
                      float2* __restrict__ stat, int nrows) {
    int wid = (blockIdx.x * blockDim.x + threadIdx.x) >> 5;
    int lane = threadIdx.x & 31;
    if (wid >= nrows) return;
    float4 v = src[(size_t)wid * 32 + lane];
    uint2 o;
    o.x = cvt_bf16x2(v.y, v.x);
    o.y = cvt_bf16x2(v.w, v.z);
    dst[(size_t)wid * 32 + lane] = o;
    float s = (v.x + v.y) + (v.z + v.w);
    float q = fmaf(v.x, v.x, fmaf(v.y, v.y, fmaf(v.z, v.z, v.w * v.w)));
    #pragma unroll
    for (int off = 16; off; off >>= 1) {
        s += __shfl_xor_sync(0xffffffffu, s, off);
        q += __shfl_xor_sync(0xffffffffu, q, off);
    }
    if (lane == 0) stat[wid] = make_float2(s, q);
}

// ---------------- prep: W' = g.*W -> bf16 swizzled; u, vb ----------------
__global__ void k_prep(const float* __restrict__ bw1, const float* __restrict__ blng,
                       const float* __restrict__ blnb, const float* __restrict__ bb1) {
    int j = blockIdx.x;     // output 0..127
    int k = threadIdx.x;    // 0..383
    __shared__ float rs[12], rv[12];
    float wraw = bw1[k * Hn + j];
    float wv = blng[k] * wraw;
    float vv = blnb[k] * wraw;
    int chunk = k >> 6, kloc = k & 63;
    uint32_t off = (uint32_t)(chunk * 16384 + j * 128 + ((kloc * 2) ^ ((j & 7) << 4)));
    *(unsigned short*)((char*)g_Wsw + off) = __bfloat16_as_ushort(__float2bfloat16(wv));
    float uu = wv;
    #pragma unroll
    for (int o = 16; o; o >>= 1) {
        uu += __shfl_xor_sync(0xffffffffu, uu, o);
        vv += __shfl_xor_sync(0xffffffffu, vv, o);
    }
    if ((k & 31) == 0) { rs[k >> 5] = uu; rv[k >> 5] = vv; }
    __syncthreads();
    if (k == 0) {
        float U = 0.f, V = 0.f;
        for (int i = 0; i < 12; i++) { U += rs[i]; V += rv[i]; }
        g_u[j] = U;
        g_vb[j] = V + bb1[j];
    }
}

// ---------------- fused start-attention + context MLP + log_z ----------------
__device__ __forceinline__ float bsum128(float v, float* red) {
    #pragma unroll
    for (int o = 16; o; o >>= 1) v += __shfl_xor_sync(0xffffffffu, v, o);
    __syncthreads();
    if ((threadIdx.x & 31) == 0) red[threadIdx.x >> 5] = v;
    __syncthreads();
    return red[0] + red[1] + red[2] + red[3];
}
__global__ void k_sctx(const float* __restrict__ nodes, const float* __restrict__ qt,
                       const int* __restrict__ locals, const int* __restrict__ ptr,
                       const float* __restrict__ cw1, const float* __restrict__ cb1,
                       const float* __restrict__ cw2, const float* __restrict__ cb2,
                       const float* __restrict__ ln1g, const float* __restrict__ ln1b,
                       const float* __restrict__ zw1, const float* __restrict__ zb1,
                       const float* __restrict__ zw2, const float* __restrict__ zb2,
                       float* __restrict__ out) {
    int g = blockIdx.x, t = threadIdx.x;  // 128 threads
    __shared__ float red[4];
    __shared__ float sc[64], salpha[64];
    __shared__ int   sidx[64];
    __shared__ float xin[256];
    __shared__ float h1[128];
    __shared__ float xh[128];
    int s0 = ptr[g], s1e = ptr[g + 1];
    int n = s1e - s0; if (n > 64) n = 64; if (n < 0) n = 0;
    float qv = qt[g * Hn + t];
    for (int s = 0; s < n; s++) {
        int nd = locals[s0 + s];
        if (t == 0) sidx[s] = nd;
        float p = nodes[nd * Hn + t] * qv;
        #pragma unroll
        for (int o = 16; o; o >>= 1) p += __shfl_xor_sync(0xffffffffu, p, o);
        if ((t & 31) == 0) red[t >> 5] = p;
        __syncthreads();
        if (t == 0) sc[s] = (red[0] + red[1] + red[2] + red[3]) * 0.08838834764831843f;
        __syncthreads();
    }
    if (t == 0) {
        float m = -INFINITY;
        for (int s = 0; s < n; s++) m = fmaxf(m, sc[s]);
        float d = 0.0f;
        for (int s = 0; s < n; s++) { float e = expf(sc[s] - m); salpha[s] = e; d += e; }
        float inv = 1.0f / d;
        for (int s = 0; s < n; s++) salpha[s] *= inv;
    }
    __syncthreads();
    float acc = 0.0f;
    for (int s = 0; s < n; s++) acc += salpha[s] * nodes[sidx[s] * Hn + t];
    xin[t] = acc;
    xin[128 + t] = qv;
    __syncthreads();
    float a0 = 0.f, a1 = 0.f, a2 = 0.f, a3 = 0.f;
    #pragma unroll 8
    for (int k = 0; k < 256; k += 4) {
        a0 = fmaf(xin[k + 0], cw1[(k + 0) * Hn + t], a0);
        a1 = fmaf(xin[k + 1], cw1[(k + 1) * Hn + t], a1);
        a2 = fmaf(xin[k + 2], cw1[(k + 2) * Hn + t], a2);
        a3 = fmaf(xin[k + 3], cw1[(k + 3) * Hn + t], a3);
    }
    h1[t] = geluf(cb1[t] + (a0 + a1) + (a2 + a3));
    __syncthreads();
    a0 = 0.f; a1 = 0.f; a2 = 0.f; a3 = 0.f;
    #pragma unroll 8
    for (int k = 0; k < 128; k += 4) {
        a0 = fmaf(h1[k + 0], cw2[(k + 0) * Hn + t], a0);
        a1 = fmaf(h1[k + 1], cw2[(k + 1) * Hn + t], a1);
        a2 = fmaf(h1[k + 2], cw2[(k + 2) * Hn + t], a2);
        a3 = fmaf(h1[k + 3], cw2[(k + 3) * Hn + t], a3);
    }
    float c = cb2[t] + (a0 + a1) + (a2 + a3);
    float mean = bsum128(c, red) * (1.0f / 128.0f);
    float d = c - mean;
    float var = bsum128(d * d, red) * (1.0f / 128.0f);
    xh[t] = d * rsqrtf(var + EPS_LN) * ln1g[t] + ln1b[t];
    __syncthreads();
    a0 = 0.f; a1 = 0.f; a2 = 0.f; a3 = 0.f;
    #pragma unroll 8
    for (int k = 0; k < 128; k += 4) {
        a0 = fmaf(xh[k + 0], zw1[(k + 0) * Hn + t], a0);
        a1 = fmaf(xh[k + 1], zw1[(k + 1) * Hn + t], a1);
        a2 = fmaf(xh[k + 2], zw1[(k + 2) * Hn + t], a2);
        a3 = fmaf(xh[k + 3], zw1[(k + 3) * Hn + t], a3);
    }
    float p = geluf(zb1[t] + (a0 + a1) + (a2 + a3)) * zw2[t];
    float lz = bsum128(p, red);
    if (t == 0) out[g * 3 + 0] = lz + zb2[0];
}

// ---------------- edge logits: bf16 GEMM; fp32 edge rows converted in-kernel ----------------
__global__ void __launch_bounds__(512, 1)
k_edge(const float* __restrict__ et,
       const int* __restrict__ ebatch, const int* __restrict__ eidx,
       const float* __restrict__ bw2, const float* __restrict__ bb2) {
    extern __shared__ char smem[];
    uint32_t sb = smem_u32(smem);
    int t = threadIdx.x, lane = t & 31;
    int w = t >> 5;
    int warp_m = w >> 1, warp_n = w & 1;

    // stage weights + params
    {
        uint4* dh = (uint4*)(smem + SM_WH);
        for (int i = t; i < 6144; i += 512) dh[i] = g_Wsw[i];
    }
    float* pu  = (float*)(smem + SM_PU);
    float* pvb = (float*)(smem + SM_PVB);
    float* pw2 = (float*)(smem + SM_PW2);
    float2* st = (float2*)(smem + SM_STAT);
    float* spart = (float*)(smem + SM_SPART);
    if (t < 128) { pu[t] = g_u[t]; pvb[t] = g_vb[t]; pw2[t] = bw2[t]; }
    __syncthreads();
    float bias2 = bb2[0];

    int r = t >> 1;                 // my row (0..255), 2 threads per row
    int hh = t & 1;                 // which half of the 64-float chunk
    uint32_t swrow = (uint32_t)((r & 7) << 4);
    uint32_t dst0 = sb + SM_A0 + r * 128;
    uint32_t dst1 = sb + SM_A1 + r * 128;

    for (int tile = blockIdx.x; tile < NT2; tile += gridDim.x) {
        int e0 = tile * TILE;
        int e = e0 + r; if (e >= NEDGES) e = NEDGES - 1;
        int br = ebatch[e], tgr = eidx[NEDGES + e];
        const char* srcQ = (const char*)(g_qbf + (size_t)br * 32);
        const char* srcN = (const char*)(g_nbf + (size_t)tgr * 32);

        // ---- edge tokens: fp32 LDG -> cvt -> STS (chunks 0,1), stats in-flight ----
        const float4* srcE = (const float4*)(et + (size_t)e * Hn) + hh * 8;
        float eS = 0.0f, eQ = 0.0f;
        #pragma unroll
        for (int c01 = 0; c01 < 2; c01++) {
            float4 fv[8];
            #pragma unroll
            for (int i = 0; i < 8; i++) fv[i] = srcE[c01 * 16 + i];
            uint32_t dst = c01 ? dst1 : dst0;
            #pragma unroll
            for (int i = 0; i < 8; i++) {
                float4 v = fv[i];
                eS += (v.x + v.y) + (v.z + v.w);
                eQ += fmaf(v.x, v.x, fmaf(v.y, v.y, fmaf(v.z, v.z, v.w * v.w)));
                uint2 H;
                H.x = cvt_bf16x2(v.y, v.x);
                H.y = cvt_bf16x2(v.w, v.z);
                uint32_t off = (uint32_t)((hh * 64 + i * 8) ^ swrow);
                *(uint2*)(smem + (dst - sb) + off) = H;
            }
        }
        // row LN stats: edge part (2-thread reduce) + node/question tables
        eS += __shfl_xor_sync(0xffffffffu, eS, 1);
        eQ += __shfl_xor_sync(0xffffffffu, eQ, 1);
        if (hh == 0) {
            float2 bq = g_qstat[br];
            float2 cn = g_nstat[tgr];
            st[r] = make_float2(eS + bq.x + cn.x, eQ + bq.y + cn.y);
        }

        float acc[2][8][4];
        #pragma unroll
        for (int a = 0; a < 2; a++)
            #pragma unroll
            for (int b = 0; b < 8; b++)
                #pragma unroll
                for (int d = 0; d < 4; d++) acc[a][b][d] = 0.0f;

        // ---- pipeline: MMA c, then cp.async c+2 into the buffer just freed ----
        #pragma unroll 1
        for (int c = 0; c < 6; c++) {
            if (c >= 2) {
                // wait for this chunk's cp.async (1 newer group may remain pending)
                if (c < 5) asm volatile("cp.async.wait_group 1;" ::: "memory");
                else       asm volatile("cp.async.wait_group 0;" ::: "memory");
            }
            __syncthreads();
            uint32_t whc = sb + SM_WH + c * 16384;
            uint32_t abb = sb + ((c & 1) ? SM_A1 : SM_A0);
            #pragma unroll
            for (int ks = 0; ks < 4; ks++) {
                uint32_t ah[2][4], bh[16];
                #pragma unroll
                for (int mt = 0; mt < 2; mt++) {
                    int row = warp_m * 32 + mt * 16 + (lane & 7) + ((lane >> 3) & 1) * 8;
                    int colb = ks * 32 + (lane >> 4) * 16;
                    LDMX4(ah[mt], abb + (uint32_t)(row * 128 + (colb ^ ((row & 7) << 4))));
                }
                #pragma unroll
                for (int bt = 0; bt < 4; bt++) {
                    int j = warp_n * 64 + bt * 16 + (lane & 7) + (lane >> 4) * 8;
                    int kb = ks * 32 + ((lane >> 3) & 1) * 16;
                    LDMX4(&bh[bt * 4], whc + (uint32_t)(j * 128 + (kb ^ ((j & 7) << 4))));
                }
                #pragma unroll
                for (int mt = 0; mt < 2; mt++)
                    #pragma unroll
                    for (int nt = 0; nt < 8; nt++)
                        mma_bf16(acc[mt][nt], ah[mt], &bh[(nt >> 1) * 4 + (nt & 1) * 2]);
            }
            __syncthreads();
            if (c < 4) {
                // issue cp.async for chunk c+2 into the buffer MMA just finished with
                int cn = c + 2;
                int part = cn >> 1, half = cn & 1;
                const char* srcp = (part == 1) ? srcQ : srcN;
                uint32_t dst = (cn & 1) ? dst1 : dst0;
                #pragma unroll
                for (int i = 0; i < 4; i++) {
                    int sg = hh * 4 + i;
                    CP16(dst + ((sg * 16) ^ swrow), srcp + half * 128 + sg * 16);
                }
                CP_COMMIT();
            }
        }

        // epilogue: folded LN + GELU + dot(w2)
        int gq = lane >> 2, cpair = (lane & 3) * 2;
        #pragma unroll
        for (int mt = 0; mt < 2; mt++) {
            #pragma unroll
            for (int half = 0; half < 2; half++) {
                int row = warp_m * 32 + mt * 16 + half * 8 + gq;
                float2 sv = st[row];
                float m = sv.x * (1.0f / 384.0f);
                float var = sv.y * (1.0f / 384.0f) - m * m;
                float is = rsqrtf(fmaxf(var, 0.0f) + EPS_LN);
                float pv = 0.0f;
                #pragma unroll
                for (int nt = 0; nt < 8; nt++) {
                    int j0 = warp_n * 64 + nt * 8 + cpair;
                    float d0 = acc[mt][nt][half * 2 + 0];
                    float d1 = acc[mt][nt][half * 2 + 1];
                    float y0 = (d0 - m * pu[j0])     * is + pvb[j0];
                    float y1 = (d1 - m * pu[j0 + 1]) * is + pvb[j0 + 1];
                    pv = fmaf(geluf(y0), pw2[j0], pv);
                    pv = fmaf(geluf(y1), pw2[j0 + 1], pv);
                }
                pv += __shfl_xor_sync(0xffffffffu, pv, 1);
                pv += __shfl_xor_sync(0xffffffffu, pv, 2);
                if ((lane & 3) == 0) spart[warp_n * 256 + row] = pv;
            }
        }
        __syncthreads();
        if (t < 256) {
            int e2 = e0 + t;
            if (e2 < NEDGES) g_logits[e2] = spart[t] + spart[256 + t] + bias2;
        }
        __syncthreads();
    }
}

// ---------------- segment exp-sum (no max shift; |logit| << 80) ----------------
__global__ void k_sexp(const int* __restrict__ eidx) {
    int e = blockIdx.x * blockDim.x + threadIdx.x;
    if (e >= NEDGES) return;
    int tg = eidx[NEDGES + e];
    atomicAdd(&g_expsum[tg], expf(g_logits[e]));
}
__global__ void k_lpb(const int* __restrict__ eidx, const int* __restrict__ ebatch,
                      const int* __restrict__ mask) {
    const int CH = 16;
    int base = (blockIdx.x * blockDim.x + threadIdx.x) * CH;
    if (base >= NEDGES) return;
    int end = base + CH; if (end > NEDGES) end = NEDGES;
    int cur = -1; float aL = 0.0f, aS = 0.0f;
    for (int e = base; e < end; e++) {
        int b = ebatch[e];
        if (b != cur) {
            if (cur >= 0 && (aL != 0.0f || aS != 0.0f)) {
                atomicAdd(&g_lpg[cur], aL);
                atomicAdd(&g_selsum[cur], aS);
            }
            cur = b; aL = 0.0f; aS = 0.0f;
        }
        if (mask[e] != 0) {
            int tg = eidx[NEDGES + e];
            float lp = g_logits[e] - logf(g_expsum[tg]);
            aL += lp; aS += 1.0f;
        }
    }
    if (cur >= 0 && (aL != 0.0f || aS != 0.0f)) {
        atomicAdd(&g_lpg[cur], aL);
        atomicAdd(&g_selsum[cur], aS);
    }
}
__global__ void k_fin(float* __restrict__ out) {
    int g = threadIdx.x;
    __shared__ float rs[32], rc[32];
    __shared__ float s_res;
    float lpg = g_lpg[g];
    float has = (g_selsum[g] > 0.0f) ? 1.0f : 0.0f;
    float v1 = -lpg * has, v2 = has;
    #pragma unroll
    for (int o = 16; o; o >>= 1) {
        v1 += __shfl_xor_sync(0xffffffffu, v1, o);
        v2 += __shfl_xor_sync(0xffffffffu, v2, o);
    }
    if ((g & 31) == 0) { rs[g >> 5] = v1; rc[g >> 5] = v2; }
    __syncthreads();
    if (g < 32) {
        float a = rs[g], b = rc[g];
        #pragma unroll
        for (int o = 16; o; o >>= 1) {
            a += __shfl_xor_sync(0xffffffffu, a, o);
            b += __shfl_xor_sync(0xffffffffu, b, o);
        }
        if (g == 0) s_res = a / fmaxf(b, 1.0f);
    }
    __syncthreads();
    out[g * 3 + 1] = lpg;
    out[g * 3 + 2] = s_res;
}

// ---------------- host ----------------
extern "C" void kernel_launch(void* const* d_in, const int* in_sizes, int n_in,
                              void* d_out, int out_size) {
    int I_node, I_q, I_edge, I_loc, I_ptr, I_eb, I_mask, I_eidx;
    int I_ln1g, I_ln1b, I_zw1, I_zb1, I_zw2, I_zb2;
    int I_cw1, I_cb1, I_cw2, I_cb2, I_blng, I_blnb, I_bw1, I_bb1, I_bw2, I_bb2;
    if (in_sizes[3] == 4096) {  // dict order
        I_node = 0; I_q = 1; I_edge = 2; I_loc = 3; I_ptr = 4; I_eb = 5; I_mask = 6; I_eidx = 7;
        I_ln1g = 8; I_ln1b = 9; I_zw1 = 10; I_zb1 = 11; I_zw2 = 12; I_zb2 = 13;
        I_cw1 = 14; I_cb1 = 15; I_cw2 = 16; I_cb2 = 17;
        I_blng = 18; I_blnb = 19; I_bw1 = 20; I_bb1 = 21; I_bw2 = 22; I_bb2 = 23;
    } else {                    // signature order
        I_node = 0; I_q = 1; I_edge = 2;
        I_ln1g = 3; I_ln1b = 4; I_zw1 = 5; I_zb1 = 6; I_zw2 = 7; I_zb2 = 8;
        I_cw1 = 9; I_cb1 = 10; I_cw2 = 11; I_cb2 = 12;
        I_blng = 13; I_blnb = 14; I_bw1 = 15; I_bb1 = 16; I_bw2 = 17; I_bb2 = 18;
        I_loc = 19; I_ptr = 20; I_eb = 21; I_mask = 22; I_eidx = 23;
    }

    const float* nodes = (const float*)d_in[I_node];
    const float* qt    = (const float*)d_in[I_q];
    const float* et    = (const float*)d_in[I_edge];
    const int*   locs  = (const int*)d_in[I_loc];
    const int*   ptr   = (const int*)d_in[I_ptr];
    const int*   ebat  = (const int*)d_in[I_eb];
    const int*   mask  = (const int*)d_in[I_mask];
    const int*   eidx  = (const int*)d_in[I_eidx];
    float* out = (float*)d_out;

    int dev = 0, nsm = 148;
    cudaGetDevice(&dev);
    cudaDeviceGetAttribute(&nsm, cudaDevAttrMultiProcessorCount, dev);

    static int smem_set = 0;
    if (!smem_set) {
        cudaFuncSetAttribute(k_edge, cudaFuncAttributeMaxDynamicSharedMemorySize, SM_TOTAL);
        smem_set = 1;
    }

    uint2* p_nbf; uint2* p_qbf;
    float2* p_nst; float2* p_qst;
    cudaGetSymbolAddress((void**)&p_nbf, g_nbf);
    cudaGetSymbolAddress((void**)&p_qbf, g_qbf);
    cudaGetSymbolAddress((void**)&p_nst, g_nstat);
    cudaGetSymbolAddress((void**)&p_qst, g_qstat);

    k_init<<<(NNODES + 255) / 256, 256>>>();
    k_prep<<<128, 384>>>((const float*)d_in[I_bw1], (const float*)d_in[I_blng],
                         (const float*)d_in[I_blnb], (const float*)d_in[I_bb1]);
    k_cvt<<<(NNODES + 7) / 8, 256>>>((const float4*)nodes, p_nbf, p_nst, NNODES);
    k_cvt<<<(Gn + 7) / 8, 256>>>((const float4*)qt, p_qbf, p_qst, Gn);
    k_sctx<<<Gn, 128>>>(nodes, qt, locs, ptr,
                        (const float*)d_in[I_cw1], (const float*)d_in[I_cb1],
                        (const float*)d_in[I_cw2], (const float*)d_in[I_cb2],
                        (const float*)d_in[I_ln1g], (const float*)d_in[I_ln1b],
                        (const float*)d_in[I_zw1], (const float*)d_in[I_zb1],
                        (const float*)d_in[I_zw2], (const float*)d_in[I_zb2],
                        out);
    k_edge<<<nsm, 512, SM_TOTAL>>>(et, ebat, eidx,
                                   (const float*)d_in[I_bw2], (const float*)d_in[I_bb2]);
    k_sexp<<<(NEDGES + 255) / 256, 256>>>(eidx);
    k_lpb<<<((NEDGES + 15) / 16 + 255) / 256, 256>>>(eidx, ebat, mask);
    k_fin<<<1, 1024>>>(out);
}